// round 10
// baseline (speedup 1.0000x reference)
#include <cuda_runtime.h>
#include <cuda_bf16.h>
#include <math.h>
#include <stdint.h>

#define D_      3072
#define H_      24
#define HD_     128
#define R_      32
#define INNER_  3072
#define QKV3_   9216
#define SIMG_   1536
#define STXT_   512
#define SALL_   2048

// scale(1/sqrt(128)) * log2(e)
#define SCALE2E_ 0.12751743f

// ---------------- scratch (device globals; no runtime allocation) ----------
static __device__ float g_qkv_img[SIMG_ * QKV3_];
static __device__ float g_qkv_txt[STXT_ * QKV3_];

// low-rank intermediates, bf16 hi/lo
static __device__ __nv_bfloat16 g_lrah[SIMG_ * R_], g_lral[SIMG_ * R_];
static __device__ __nv_bfloat16 g_lrbh[STXT_ * R_], g_lrbl[STXT_ * R_];

// transposed up-projection matrices [N,32] bf16 hi/lo
static __device__ __nv_bfloat16 g_UTqh[QKV3_ * R_],  g_UTql[QKV3_ * R_];
static __device__ __nv_bfloat16 g_UTaqh[QKV3_ * R_], g_UTaql[QKV3_ * R_];
static __device__ __nv_bfloat16 g_UToh[D_ * R_],     g_UTol[D_ * R_];
static __device__ __nv_bfloat16 g_UTaoh[D_ * R_],    g_UTaol[D_ * R_];

// attention operands, bf16 hi/lo, layout [H][SALL][HD]
static __device__ __nv_bfloat16 g_qh[H_ * SALL_ * HD_], g_ql[H_ * SALL_ * HD_];
static __device__ __nv_bfloat16 g_kh[H_ * SALL_ * HD_], g_kl[H_ * SALL_ * HD_];
static __device__ __nv_bfloat16 g_vh[H_ * SALL_ * HD_], g_vl[H_ * SALL_ * HD_];

// attention output, bf16 hi/lo, [SALL][INNER] (txt rows 0..511, img 512..2047)
static __device__ __nv_bfloat16 g_ACh[SALL_ * INNER_], g_ACl[SALL_ * INNER_];

// bf16 hi/lo split buffers for projection GEMM inputs
static __device__ __nv_bfloat16 g_Aih[SIMG_ * D_],  g_Ail[SIMG_ * D_];
static __device__ __nv_bfloat16 g_Ath[STXT_ * D_],  g_Atl[STXT_ * D_];
static __device__ __nv_bfloat16 g_Bqh[QKV3_ * D_],  g_Bql[QKV3_ * D_];
static __device__ __nv_bfloat16 g_Baqh[QKV3_ * D_], g_Baql[QKV3_ * D_];
static __device__ __nv_bfloat16 g_Boh[D_ * INNER_], g_Bol[D_ * INNER_];
static __device__ __nv_bfloat16 g_Baoh[D_ * INNER_], g_Baol[D_ * INNER_];

// ---------------------------------------------------------------------------
// fp32 -> bf16 hi/lo split
// ---------------------------------------------------------------------------
__global__ void __launch_bounds__(256) split_bf16_kernel(
    const float* __restrict__ X, __nv_bfloat16* __restrict__ Xh,
    __nv_bfloat16* __restrict__ Xl, int n4)
{
    int i = blockIdx.x * blockDim.x + threadIdx.x;
    if (i >= n4) return;
    float4 v = ((const float4*)X)[i];
    union { __nv_bfloat16 b[4]; uint2 u; } ph, pl;
    ph.b[0] = __float2bfloat16(v.x);
    ph.b[1] = __float2bfloat16(v.y);
    ph.b[2] = __float2bfloat16(v.z);
    ph.b[3] = __float2bfloat16(v.w);
    pl.b[0] = __float2bfloat16(v.x - __bfloat162float(ph.b[0]));
    pl.b[1] = __float2bfloat16(v.y - __bfloat162float(ph.b[1]));
    pl.b[2] = __float2bfloat16(v.z - __bfloat162float(ph.b[2]));
    pl.b[3] = __float2bfloat16(v.w - __bfloat162float(ph.b[3]));
    ((uint2*)Xh)[i] = ph.u;
    ((uint2*)Xl)[i] = pl.u;
}

// transpose + split: U[32,N] fp32 -> UT[N,32] bf16 hi/lo
__global__ void __launch_bounds__(256) tsplit_kernel(
    const float* __restrict__ U, __nv_bfloat16* __restrict__ UTh,
    __nv_bfloat16* __restrict__ UTl, int N)
{
    int idx = blockIdx.x * blockDim.x + threadIdx.x;   // idx = k*N + n
    if (idx >= 32 * N) return;
    int n = idx % N, k = idx / N;
    float v = U[idx];
    __nv_bfloat16 h = __float2bfloat16(v);
    UTh[(size_t)n * 32 + k] = h;
    UTl[(size_t)n * 32 + k] = __float2bfloat16(v - __bfloat162float(h));
}

// ---------------------------------------------------------------------------
// helpers
// ---------------------------------------------------------------------------
__device__ __forceinline__ uint32_t sptr(const void* p) {
    return (uint32_t)__cvta_generic_to_shared(p);
}
__device__ __forceinline__ void ldsm_x4(uint32_t* r, uint32_t a) {
    asm volatile("ldmatrix.sync.aligned.m8n8.x4.shared.b16 {%0,%1,%2,%3}, [%4];"
                 : "=r"(r[0]), "=r"(r[1]), "=r"(r[2]), "=r"(r[3]) : "r"(a));
}
__device__ __forceinline__ void ldsm_x4_t(uint32_t* r, uint32_t a) {
    asm volatile("ldmatrix.sync.aligned.m8n8.x4.trans.shared.b16 {%0,%1,%2,%3}, [%4];"
                 : "=r"(r[0]), "=r"(r[1]), "=r"(r[2]), "=r"(r[3]) : "r"(a));
}
__device__ __forceinline__ void mma_bf16(float* c, const uint32_t* a,
                                         uint32_t b0, uint32_t b1) {
    asm volatile(
        "mma.sync.aligned.m16n8k16.row.col.f32.bf16.bf16.f32 "
        "{%0,%1,%2,%3},{%4,%5,%6,%7},{%8,%9},{%0,%1,%2,%3};"
        : "+f"(c[0]), "+f"(c[1]), "+f"(c[2]), "+f"(c[3])
        : "r"(a[0]), "r"(a[1]), "r"(a[2]), "r"(a[3]), "r"(b0), "r"(b1));
}
__device__ __forceinline__ uint32_t packbf(float lo, float hi) {
    uint32_t r;
    asm("cvt.rn.bf16x2.f32 %0, %1, %2;" : "=r"(r) : "f"(hi), "f"(lo));
    return r;
}
__device__ __forceinline__ float lobf(uint32_t r) { return __uint_as_float(r << 16); }
__device__ __forceinline__ float hibf(uint32_t r) { return __uint_as_float(r & 0xffff0000u); }
__device__ __forceinline__ void cpa16(uint32_t d, const void* g) {
    asm volatile("cp.async.cg.shared.global [%0], [%1], 16;" :: "r"(d), "l"(g));
}

// ---------------------------------------------------------------------------
// GEMM with low-rank fold:
//   C[M,N] = A[M,K] @ B[N,K]^T + LR[M,32] @ UT[N,32]^T (+bias)
// all operands bf16 hi/lo, 3-product per pair. 128x128 tile, k-chunk 32,
// 3-stage cp.async pipeline. 8 warps (2M x 4N), warp tile 64x32.
// grid (N/128, M/128).
// ---------------------------------------------------------------------------
#define GTILE_  10240            // one 128 x 40-half tile in bytes
#define GSTAGE_ (4 * GTILE_)     // Ah, Al, Bh, Bl
#define GEMM_SMEM_ (3 * GSTAGE_)

__global__ void __launch_bounds__(256, 1) gemm_mma2_kernel(
    const __nv_bfloat16* __restrict__ Ah, const __nv_bfloat16* __restrict__ Al,
    const __nv_bfloat16* __restrict__ Bh, const __nv_bfloat16* __restrict__ Bl,
    const __nv_bfloat16* __restrict__ LRh, const __nv_bfloat16* __restrict__ LRl,
    const __nv_bfloat16* __restrict__ UTh, const __nv_bfloat16* __restrict__ UTl,
    const float* __restrict__ bias, float* __restrict__ C,
    int M, int N, int K)
{
    extern __shared__ char gsm[];
    const int tid  = threadIdx.x;
    const int brow = blockIdx.y * 128;
    const int bcol = blockIdx.x * 128;
    const int warp = tid >> 5, lane = tid & 31;
    const int wm = (warp & 1) * 64;
    const int wn = (warp >> 1) * 32;

    const int lrow = tid >> 2;           // 0..63 (and +64)
    const int lseg = (tid & 3) * 8;      // half offset 0,8,16,24
    const int segb = (tid & 3) * 16;     // byte offset in smem row

    const int nkmain = K >> 5;
    const int nk = nkmain + 1;           // + low-rank chunk

    auto issue_chunk = [&](int c) {
        char* buf = gsm + (c % 3) * GSTAGE_;
        const __nv_bfloat16 *pa0, *pa1, *pb0, *pb1;
        int sA, sB, koff;
        if (c < nkmain) {
            pa0 = Ah; pa1 = Al; pb0 = Bh; pb1 = Bl;
            sA = K; sB = K; koff = c * 32;
        } else {
            pa0 = LRh; pa1 = LRl; pb0 = UTh; pb1 = UTl;
            sA = 32; sB = 32; koff = 0;
        }
        const uint32_t s0 = sptr(buf);
        const int r0b = lrow * 80 + segb;
        const int r1b = (lrow + 64) * 80 + segb;
        cpa16(s0 + r0b,              pa0 + (size_t)(brow + lrow) * sA + koff + lseg);
        cpa16(s0 + r1b,              pa0 + (size_t)(brow + lrow + 64) * sA + koff + lseg);
        cpa16(s0 + GTILE_ + r0b,     pa1 + (size_t)(brow + lrow) * sA + koff + lseg);
        cpa16(s0 + GTILE_ + r1b,     pa1 + (size_t)(brow + lrow + 64) * sA + koff + lseg);
        cpa16(s0 + 2 * GTILE_ + r0b, pb0 + (size_t)(bcol + lrow) * sB + koff + lseg);
        cpa16(s0 + 2 * GTILE_ + r1b, pb0 + (size_t)(bcol + lrow + 64) * sB + koff + lseg);
        cpa16(s0 + 3 * GTILE_ + r0b, pb1 + (size_t)(bcol + lrow) * sB + koff + lseg);
        cpa16(s0 + 3 * GTILE_ + r1b, pb1 + (size_t)(bcol + lrow + 64) * sB + koff + lseg);
        asm volatile("cp.async.commit_group;");
    };

    float acc[4][4][4];
#pragma unroll
    for (int i = 0; i < 4; i++)
#pragma unroll
        for (int j = 0; j < 4; j++)
#pragma unroll
            for (int e = 0; e < 4; e++) acc[i][j][e] = 0.f;

    const int qa = lane >> 3, ra = lane & 7;
    const int a_row = (qa & 1) * 8 + ra;
    const int a_col = (qa >> 1) * 8;
    const int b_row = (qa >> 1) * 8 + ra;
    const int b_col = (qa & 1) * 8;

    issue_chunk(0);
    issue_chunk(1);

    for (int c = 0; c < nk; c++) {
        if (c + 1 < nk) asm volatile("cp.async.wait_group 1;");
        else            asm volatile("cp.async.wait_group 0;");
        __syncthreads();

        __nv_bfloat16* sAh = (__nv_bfloat16*)(gsm + (c % 3) * GSTAGE_);
        __nv_bfloat16* sAl = sAh + 5120;
        __nv_bfloat16* sBh = sAh + 10240;
        __nv_bfloat16* sBl = sAh + 15360;

#pragma unroll
        for (int kb = 0; kb < 32; kb += 16) {
            uint32_t ah[4][4], al[4][4], bh[2][4], bl[2][4];
#pragma unroll
            for (int mf = 0; mf < 4; mf++) {
                int r = wm + mf * 16 + a_row;
                ldsm_x4(ah[mf], sptr(&sAh[r * 40 + kb + a_col]));
                ldsm_x4(al[mf], sptr(&sAl[r * 40 + kb + a_col]));
            }
#pragma unroll
            for (int p = 0; p < 2; p++) {
                int r = wn + p * 16 + b_row;
                ldsm_x4(bh[p], sptr(&sBh[r * 40 + kb + b_col]));
                ldsm_x4(bl[p], sptr(&sBl[r * 40 + kb + b_col]));
            }
#pragma unroll
            for (int mf = 0; mf < 4; mf++)
#pragma unroll
                for (int nf = 0; nf < 4; nf++) {
                    const int p = nf >> 1, o = (nf & 1) * 2;
                    mma_bf16(acc[mf][nf], ah[mf], bh[p][o], bh[p][o + 1]);
                    mma_bf16(acc[mf][nf], ah[mf], bl[p][o], bl[p][o + 1]);
                    mma_bf16(acc[mf][nf], al[mf], bh[p][o], bh[p][o + 1]);
                }
        }
        __syncthreads();
        if (c + 2 < nk) issue_chunk(c + 2);
    }

    const int g = lane >> 2, t = lane & 3;
#pragma unroll
    for (int mf = 0; mf < 4; mf++) {
        int r0 = brow + wm + mf * 16 + g;
#pragma unroll
        for (int nf = 0; nf < 4; nf++) {
            int col = bcol + wn + nf * 8 + t * 2;
            float b0 = 0.f, b1 = 0.f;
            if (bias) { b0 = bias[col]; b1 = bias[col + 1]; }
            float2 v0, v1;
            v0.x = acc[mf][nf][0] + b0; v0.y = acc[mf][nf][1] + b1;
            v1.x = acc[mf][nf][2] + b0; v1.y = acc[mf][nf][3] + b1;
            *(float2*)(C + (size_t)r0 * N + col)       = v0;
            *(float2*)(C + (size_t)(r0 + 8) * N + col) = v1;
        }
    }
}

// ---------------------------------------------------------------------------
// down-proj: C[M,32] = A[M,K] @ B[K,32], output bf16 hi/lo. fp32-input variant.
// ---------------------------------------------------------------------------
__global__ void __launch_bounds__(256) down_proj_f32_kernel(
    const float* __restrict__ A, const float* __restrict__ B,
    __nv_bfloat16* __restrict__ Ch, __nv_bfloat16* __restrict__ Cl, int K)
{
    const int m = blockIdx.x;
    const int c = threadIdx.x & 31;
    const int kc = threadIdx.x >> 5;
    const float* a = A + (size_t)m * K;
    const int kchunk = K >> 3;
    const int k0 = kc * kchunk;
    float s = 0.f;
    for (int k = k0; k < k0 + kchunk; k++)
        s += a[k] * B[k * R_ + c];
    __shared__ float red[256];
    red[threadIdx.x] = s;
    __syncthreads();
    if (kc == 0) {
        float t = s;
#pragma unroll
        for (int i = 1; i < 8; i++) t += red[i * 32 + c];
        __nv_bfloat16 h = __float2bfloat16(t);
        Ch[m * R_ + c] = h;
        Cl[m * R_ + c] = __float2bfloat16(t - __bfloat162float(h));
    }
}

// bf16 hi/lo-input variant
__global__ void __launch_bounds__(256) down_proj_bf_kernel(
    const __nv_bfloat16* __restrict__ Ah, const __nv_bfloat16* __restrict__ Al,
    const float* __restrict__ B,
    __nv_bfloat16* __restrict__ Ch, __nv_bfloat16* __restrict__ Cl, int K)
{
    const int m = blockIdx.x;
    const int c = threadIdx.x & 31;
    const int kc = threadIdx.x >> 5;
    const __nv_bfloat16* ah = Ah + (size_t)m * K;
    const __nv_bfloat16* al = Al + (size_t)m * K;
    const int kchunk = K >> 3;
    const int k0 = kc * kchunk;
    float s = 0.f;
    for (int k = k0; k < k0 + kchunk; k++)
        s += (__bfloat162float(ah[k]) + __bfloat162float(al[k])) * B[k * R_ + c];
    __shared__ float red[256];
    red[threadIdx.x] = s;
    __syncthreads();
    if (kc == 0) {
        float t = s;
#pragma unroll
        for (int i = 1; i < 8; i++) t += red[i * 32 + c];
        __nv_bfloat16 h = __float2bfloat16(t);
        Ch[m * R_ + c] = h;
        Cl[m * R_ + c] = __float2bfloat16(t - __bfloat162float(h));
    }
}

// ---------------------------------------------------------------------------
// QKV post: heads, RMSNorm, RoPE; writes bf16 hi/lo Q(scaled)/K/V to [H][S][HD]
// ---------------------------------------------------------------------------
__global__ void __launch_bounds__(128) qkv_post_kernel(
    const float* __restrict__ qkv, int pos_off,
    const float* __restrict__ wq, const float* __restrict__ wk,
    const float* __restrict__ rcos, const float* __restrict__ rsin,
    __nv_bfloat16* __restrict__ qh, __nv_bfloat16* __restrict__ ql,
    __nv_bfloat16* __restrict__ kh, __nv_bfloat16* __restrict__ kl,
    __nv_bfloat16* __restrict__ vh, __nv_bfloat16* __restrict__ vl)
{
    const int s = blockIdx.x;
    const int h = blockIdx.y;
    const int d = threadIdx.x;
    const float* row = qkv + (size_t)s * QKV3_ + h * HD_;
    float q = row[d];
    float k = row[INNER_ + d];
    float v = row[2 * INNER_ + d];

    __shared__ float sh[8];
    float sq = q * q, sk = k * k;
#pragma unroll
    for (int o = 16; o > 0; o >>= 1) {
        sq += __shfl_xor_sync(0xffffffffu, sq, o);
        sk += __shfl_xor_sync(0xffffffffu, sk, o);
    }
    int w = d >> 5;
    if ((d & 31) == 0) { sh[w] = sq; sh[4 + w] = sk; }
    __syncthreads();
    sq = sh[0] + sh[1] + sh[2] + sh[3];
    sk = sh[4] + sh[5] + sh[6] + sh[7];
    float rq = rsqrtf(sq * (1.f / HD_) + 1e-5f);
    float rk = rsqrtf(sk * (1.f / HD_) + 1e-5f);
    q = q * rq * wq[d];
    k = k * rk * wk[d];

    const int pos = pos_off + s;
    float c = rcos[pos * 64 + (d >> 1)];
    float sn = rsin[pos * 64 + (d >> 1)];
    float qo = __shfl_xor_sync(0xffffffffu, q, 1);
    float ko = __shfl_xor_sync(0xffffffffu, k, 1);
    float qr = (d & 1) ? (qo * sn + q * c) : (q * c - qo * sn);
    float kr = (d & 1) ? (ko * sn + k * c) : (k * c - ko * sn);

    qr *= SCALE2E_;

    size_t o = ((size_t)h * SALL_ + pos) * HD_ + d;
    __nv_bfloat16 hq = __float2bfloat16(qr);
    __nv_bfloat16 hk = __float2bfloat16(kr);
    __nv_bfloat16 hv = __float2bfloat16(v);
    qh[o] = hq; ql[o] = __float2bfloat16(qr - __bfloat162float(hq));
    kh[o] = hk; kl[o] = __float2bfloat16(kr - __bfloat162float(hk));
    vh[o] = hv; vl[o] = __float2bfloat16(v  - __bfloat162float(hv));
}

// ---------------------------------------------------------------------------
// Tensor-core flash attention (mma.sync). Epilogue writes bf16 hi/lo.
// ---------------------------------------------------------------------------
#define ALDA_ 136
#define ATTN_SMEM_ ((2 * 128 + 4 * 64) * ALDA_ * 2)

__global__ void __launch_bounds__(256, 1) attn_mma_kernel(
    const __nv_bfloat16* __restrict__ Qh, const __nv_bfloat16* __restrict__ Ql,
    const __nv_bfloat16* __restrict__ Kh, const __nv_bfloat16* __restrict__ Kl,
    const __nv_bfloat16* __restrict__ Vh, const __nv_bfloat16* __restrict__ Vl,
    __nv_bfloat16* __restrict__ Oh, __nv_bfloat16* __restrict__ Ol)
{
    extern __shared__ __nv_bfloat16 sbuf[];
    __nv_bfloat16* sQh = sbuf;
    __nv_bfloat16* sQl = sQh + 128 * ALDA_;
    __nv_bfloat16* sKh = sQl + 128 * ALDA_;
    __nv_bfloat16* sKl = sKh + 64 * ALDA_;
    __nv_bfloat16* sVh = sKl + 64 * ALDA_;
    __nv_bfloat16* sVl = sVh + 64 * ALDA_;

    const int head = blockIdx.y;
    const int q0 = blockIdx.x * 128;
    const int tid = threadIdx.x;
    const int warp = tid >> 5, lane = tid & 31;
    const size_t hbase = (size_t)head * SALL_ * HD_;

    {
        const uint4* gqh = (const uint4*)(Qh + hbase + (size_t)q0 * HD_);
        const uint4* gql = (const uint4*)(Ql + hbase + (size_t)q0 * HD_);
#pragma unroll
        for (int k = 0; k < 8; k++) {
            int i = tid + k * 256;
            int row = i >> 4, seg = i & 15;
            *(uint4*)&sQh[row * ALDA_ + seg * 8] = gqh[i];
            *(uint4*)&sQl[row * ALDA_ + seg * 8] = gql[i];
        }
    }

    float accO[16][4];
#pragma unroll
    for (int i = 0; i < 16; i++)
#pragma unroll
        for (int e = 0; e < 4; e++) accO[i][e] = 0.f;
    float m0 = -1e30f, m1 = -1e30f, l0 = 0.f, l1 = 0.f;

    const int qa = lane >> 3, ra = lane & 7;
    const int arow = warp * 16 + (qa & 1) * 8 + ra;
    const int acol = (qa >> 1) * 8;
    const int vrow = lane & 15;
    const int vcol = (lane >> 4) * 8;

    for (int kt = 0; kt < SALL_ / 64; kt++) {
        __syncthreads();
        {
            const size_t kvoff = hbase + (size_t)(kt * 64) * HD_;
            const uint4* gkh = (const uint4*)(Kh + kvoff);
            const uint4* gkl = (const uint4*)(Kl + kvoff);
            const uint4* gvh = (const uint4*)(Vh + kvoff);
            const uint4* gvl = (const uint4*)(Vl + kvoff);
#pragma unroll
            for (int k = 0; k < 4; k++) {
                int i = tid + k * 256;
                int row = i >> 4, seg = i & 15;
                int dst = row * ALDA_ + seg * 8;
                *(uint4*)&sKh[dst] = gkh[i];
                *(uint4*)&sKl[dst] = gkl[i];
                *(uint4*)&sVh[dst] = gvh[i];
                *(uint4*)&sVl[dst] = gvl[i];
            }
        }
        __syncthreads();

        float accS[8][4];
#pragma unroll
        for (int j = 0; j < 8; j++)
#pragma unroll
            for (int e = 0; e < 4; e++) accS[j][e] = 0.f;

#pragma unroll
        for (int kc = 0; kc < 8; kc++) {
            uint32_t ah[4], al[4];
            ldsm_x4(ah, sptr(&sQh[arow * ALDA_ + kc * 16 + acol]));
            ldsm_x4(al, sptr(&sQl[arow * ALDA_ + kc * 16 + acol]));
#pragma unroll
            for (int np = 0; np < 4; np++) {
                uint32_t bh[4], bl[4];
                int br = np * 16 + (qa & 1) * 8 + ra;
                ldsm_x4(bh, sptr(&sKh[br * ALDA_ + kc * 16 + acol]));
                ldsm_x4(bl, sptr(&sKl[br * ALDA_ + kc * 16 + acol]));
                mma_bf16(accS[2 * np],     ah, bh[0], bh[2]);
                mma_bf16(accS[2 * np],     ah, bl[0], bl[2]);
                mma_bf16(accS[2 * np],     al, bh[0], bh[2]);
                mma_bf16(accS[2 * np + 1], ah, bh[1], bh[3]);
                mma_bf16(accS[2 * np + 1], ah, bl[1], bl[3]);
                mma_bf16(accS[2 * np + 1], al, bh[1], bh[3]);
            }
        }

        float ml0 = -1e30f, ml1 = -1e30f;
#pragma unroll
        for (int j = 0; j < 8; j++) {
            ml0 = fmaxf(ml0, fmaxf(accS[j][0], accS[j][1]));
            ml1 = fmaxf(ml1, fmaxf(accS[j][2], accS[j][3]));
        }
#pragma unroll
        for (int o = 1; o < 4; o <<= 1) {
            ml0 = fmaxf(ml0, __shfl_xor_sync(0xffffffffu, ml0, o));
            ml1 = fmaxf(ml1, __shfl_xor_sync(0xffffffffu, ml1, o));
        }
        float mn0 = fmaxf(m0, ml0), mn1 = fmaxf(m1, ml1);
        float f0 = exp2f(m0 - mn0), f1 = exp2f(m1 - mn1);
        float s0 = 0.f, s1 = 0.f;
#pragma unroll
        for (int j = 0; j < 8; j++) {
            accS[j][0] = exp2f(accS[j][0] - mn0);
            accS[j][1] = exp2f(accS[j][1] - mn0);
            accS[j][2] = exp2f(accS[j][2] - mn1);
            accS[j][3] = exp2f(accS[j][3] - mn1);
            s0 += accS[j][0] + accS[j][1];
            s1 += accS[j][2] + accS[j][3];
        }
#pragma unroll
        for (int o = 1; o < 4; o <<= 1) {
            s0 += __shfl_xor_sync(0xffffffffu, s0, o);
            s1 += __shfl_xor_sync(0xffffffffu, s1, o);
        }
        l0 = l0 * f0 + s0; l1 = l1 * f1 + s1;
        m0 = mn0; m1 = mn1;
#pragma unroll
        for (int i = 0; i < 16; i++) {
            accO[i][0] *= f0; accO[i][1] *= f0;
            accO[i][2] *= f1; accO[i][3] *= f1;
        }

#pragma unroll
        for (int kc2 = 0; kc2 < 4; kc2++) {
            const int j0 = 2 * kc2, j1 = j0 + 1;
            uint32_t pah[4], pal[4];
            pah[0] = packbf(accS[j0][0], accS[j0][1]);
            pah[1] = packbf(accS[j0][2], accS[j0][3]);
            pah[2] = packbf(accS[j1][0], accS[j1][1]);
            pah[3] = packbf(accS[j1][2], accS[j1][3]);
            pal[0] = packbf(accS[j0][0] - lobf(pah[0]), accS[j0][1] - hibf(pah[0]));
            pal[1] = packbf(accS[j0][2] - lobf(pah[1]), accS[j0][3] - hibf(pah[1]));
            pal[2] = packbf(accS[j1][0] - lobf(pah[2]), accS[j1][1] - hibf(pah[2]));
            pal[3] = packbf(accS[j1][2] - lobf(pah[3]), accS[j1][3] - hibf(pah[3]));

            const int vr = kc2 * 16 + vrow;
#pragma unroll
            for (int np = 0; np < 8; np++) {
                uint32_t vbh[4], vbl[4];
                ldsm_x4_t(vbh, sptr(&sVh[vr * ALDA_ + np * 16 + vcol]));
                ldsm_x4_t(vbl, sptr(&sVl[vr * ALDA_ + np * 16 + vcol]));
                mma_bf16(accO[2 * np],     pah, vbh[0], vbh[1]);
                mma_bf16(accO[2 * np],     pah, vbl[0], vbl[1]);
                mma_bf16(accO[2 * np],     pal, vbh[0], vbh[1]);
                mma_bf16(accO[2 * np + 1], pah, vbh[2], vbh[3]);
                mma_bf16(accO[2 * np + 1], pah, vbl[2], vbl[3]);
                mma_bf16(accO[2 * np + 1], pal, vbh[2], vbh[3]);
            }
        }
    }

    // epilogue: normalize and emit bf16 hi/lo directly (saves split pass)
    const float inv0 = 1.f / l0, inv1 = 1.f / l1;
    const int r0 = q0 + warp * 16 + (lane >> 2);
    const int cb = head * HD_ + (lane & 3) * 2;
#pragma unroll
    for (int nt = 0; nt < 16; nt++) {
        float x0 = accO[nt][0] * inv0, y0 = accO[nt][1] * inv0;
        float x1 = accO[nt][2] * inv1, y1 = accO[nt][3] * inv1;
        uint32_t h0 = packbf(x0, y0);
        uint32_t e0 = packbf(x0 - lobf(h0), y0 - hibf(h0));
        uint32_t h1 = packbf(x1, y1);
        uint32_t e1 = packbf(x1 - lobf(h1), y1 - hibf(h1));
        size_t o0 = (size_t)r0 * INNER_ + cb + nt * 8;
        size_t o1 = (size_t)(r0 + 8) * INNER_ + cb + nt * 8;
        *(uint32_t*)&Oh[o0] = h0;  *(uint32_t*)&Ol[o0] = e0;
        *(uint32_t*)&Oh[o1] = h1;  *(uint32_t*)&Ol[o1] = e1;
    }
}

// ---------------------------------------------------------------------------
static inline void split_launch(const float* X, __nv_bfloat16* h, __nv_bfloat16* l,
                                long long n)
{
    int n4 = (int)(n >> 2);
    split_bf16_kernel<<<(n4 + 255) / 256, 256>>>(X, h, l, n4);
}

static inline void gemm_lr(const __nv_bfloat16* Ah, const __nv_bfloat16* Al,
                           const __nv_bfloat16* Bh, const __nv_bfloat16* Bl,
                           const __nv_bfloat16* LRh, const __nv_bfloat16* LRl,
                           const __nv_bfloat16* UTh, const __nv_bfloat16* UTl,
                           const float* bias, float* C, int M, int N, int K)
{
    cudaFuncSetAttribute(gemm_mma2_kernel, cudaFuncAttributeMaxDynamicSharedMemorySize,
                         GEMM_SMEM_);
    gemm_mma2_kernel<<<dim3(N / 128, M / 128), 256, GEMM_SMEM_>>>(
        Ah, Al, Bh, Bl, LRh, LRl, UTh, UTl, bias, C, M, N, K);
}

extern "C" void kernel_launch(void* const* d_in, const int* in_sizes, int n_in,
                              void* d_out, int out_size)
{
    const float* hs        = (const float*)d_in[0];
    const float* ehs       = (const float*)d_in[1];
    const float* rcos      = (const float*)d_in[2];
    const float* rsin      = (const float*)d_in[3];
    const float* qkv_w     = (const float*)d_in[4];
    const float* qkv_down  = (const float*)d_in[5];
    const float* qkv_up    = (const float*)d_in[6];
    const float* aqkv_w    = (const float*)d_in[7];
    const float* aqkv_down = (const float*)d_in[8];
    const float* aqkv_up   = (const float*)d_in[9];
    const float* out_w     = (const float*)d_in[10];
    const float* out_down  = (const float*)d_in[11];
    const float* out_up    = (const float*)d_in[12];
    const float* out_b     = (const float*)d_in[13];
    const float* aout_w    = (const float*)d_in[14];
    const float* aout_down = (const float*)d_in[15];
    const float* aout_up   = (const float*)d_in[16];
    const float* aout_b    = (const float*)d_in[17];
    const float* nq        = (const float*)d_in[18];
    const float* nk        = (const float*)d_in[19];
    const float* naq       = (const float*)d_in[20];
    const float* nak       = (const float*)d_in[21];

    float *qkv_img, *qkv_txt;
    cudaGetSymbolAddress((void**)&qkv_img, g_qkv_img);
    cudaGetSymbolAddress((void**)&qkv_txt, g_qkv_txt);

    __nv_bfloat16 *lrah, *lral, *lrbh, *lrbl;
    cudaGetSymbolAddress((void**)&lrah, g_lrah);
    cudaGetSymbolAddress((void**)&lral, g_lral);
    cudaGetSymbolAddress((void**)&lrbh, g_lrbh);
    cudaGetSymbolAddress((void**)&lrbl, g_lrbl);

    __nv_bfloat16 *UTqh, *UTql, *UTaqh, *UTaql, *UToh, *UTol, *UTaoh, *UTaol;
    cudaGetSymbolAddress((void**)&UTqh, g_UTqh);
    cudaGetSymbolAddress((void**)&UTql, g_UTql);
    cudaGetSymbolAddress((void**)&UTaqh, g_UTaqh);
    cudaGetSymbolAddress((void**)&UTaql, g_UTaql);
    cudaGetSymbolAddress((void**)&UToh, g_UToh);
    cudaGetSymbolAddress((void**)&UTol, g_UTol);
    cudaGetSymbolAddress((void**)&UTaoh, g_UTaoh);
    cudaGetSymbolAddress((void**)&UTaol, g_UTaol);

    __nv_bfloat16 *qbh, *qbl, *kbh, *kbl, *vbh, *vbl, *ACh, *ACl;
    cudaGetSymbolAddress((void**)&qbh, g_qh);
    cudaGetSymbolAddress((void**)&qbl, g_ql);
    cudaGetSymbolAddress((void**)&kbh, g_kh);
    cudaGetSymbolAddress((void**)&kbl, g_kl);
    cudaGetSymbolAddress((void**)&vbh, g_vh);
    cudaGetSymbolAddress((void**)&vbl, g_vl);
    cudaGetSymbolAddress((void**)&ACh, g_ACh);
    cudaGetSymbolAddress((void**)&ACl, g_ACl);

    __nv_bfloat16 *Aih, *Ail, *Ath, *Atl;
    __nv_bfloat16 *Bqh, *Bql, *Baqh, *Baql, *Boh, *Bol, *Baoh, *Baol;
    cudaGetSymbolAddress((void**)&Aih, g_Aih);
    cudaGetSymbolAddress((void**)&Ail, g_Ail);
    cudaGetSymbolAddress((void**)&Ath, g_Ath);
    cudaGetSymbolAddress((void**)&Atl, g_Atl);
    cudaGetSymbolAddress((void**)&Bqh, g_Bqh);
    cudaGetSymbolAddress((void**)&Bql, g_Bql);
    cudaGetSymbolAddress((void**)&Baqh, g_Baqh);
    cudaGetSymbolAddress((void**)&Baql, g_Baql);
    cudaGetSymbolAddress((void**)&Boh, g_Boh);
    cudaGetSymbolAddress((void**)&Bol, g_Bol);
    cudaGetSymbolAddress((void**)&Baoh, g_Baoh);
    cudaGetSymbolAddress((void**)&Baol, g_Baol);

    float* out_img = (float*)d_out;
    float* out_txt = (float*)d_out + (size_t)SIMG_ * D_;

    // ---- conversions ----
    split_launch(hs,     Aih,  Ail,  (long long)SIMG_ * D_);
    split_launch(ehs,    Ath,  Atl,  (long long)STXT_ * D_);
    split_launch(qkv_w,  Bqh,  Bql,  (long long)QKV3_ * D_);
    split_launch(aqkv_w, Baqh, Baql, (long long)QKV3_ * D_);
    split_launch(out_w,  Boh,  Bol,  (long long)D_ * INNER_);
    split_launch(aout_w, Baoh, Baol, (long long)D_ * INNER_);
    tsplit_kernel<<<(32 * QKV3_ + 255) / 256, 256>>>(qkv_up,  UTqh,  UTql,  QKV3_);
    tsplit_kernel<<<(32 * QKV3_ + 255) / 256, 256>>>(aqkv_up, UTaqh, UTaql, QKV3_);
    tsplit_kernel<<<(32 * D_ + 255) / 256, 256>>>(out_up,  UToh,  UTol,  D_);
    tsplit_kernel<<<(32 * D_ + 255) / 256, 256>>>(aout_up, UTaoh, UTaol, D_);

    // ---- QKV projections (dense + low-rank folded into one GEMM) ----
    down_proj_f32_kernel<<<SIMG_, 256>>>(hs, qkv_down, lrah, lral, D_);
    gemm_lr(Aih, Ail, Bqh, Bql, lrah, lral, UTqh, UTql, nullptr,
            qkv_img, SIMG_, QKV3_, D_);
    down_proj_f32_kernel<<<STXT_, 256>>>(ehs, aqkv_down, lrbh, lrbl, D_);
    gemm_lr(Ath, Atl, Baqh, Baql, lrbh, lrbl, UTaqh, UTaql, nullptr,
            qkv_txt, STXT_, QKV3_, D_);

    // ---- heads + RMSNorm + RoPE -> bf16 hi/lo Q/K/V (txt first, then img) ----
    qkv_post_kernel<<<dim3(STXT_, H_), 128>>>(qkv_txt, 0, naq, nak, rcos, rsin,
                                              qbh, qbl, kbh, kbl, vbh, vbl);
    qkv_post_kernel<<<dim3(SIMG_, H_), 128>>>(qkv_img, STXT_, nq, nk, rcos, rsin,
                                              qbh, qbl, kbh, kbl, vbh, vbl);

    // ---- tensor-core attention (emits bf16 hi/lo activations) ----
    cudaFuncSetAttribute(attn_mma_kernel, cudaFuncAttributeMaxDynamicSharedMemorySize,
                         ATTN_SMEM_);
    attn_mma_kernel<<<dim3(SALL_ / 128, H_), 256, ATTN_SMEM_>>>(
        qbh, qbl, kbh, kbl, vbh, vbl, ACh, ACl);

    // ---- output projections ----
    const __nv_bfloat16* Aimgh = ACh + (size_t)STXT_ * INNER_;
    const __nv_bfloat16* Aimgl = ACl + (size_t)STXT_ * INNER_;
    const __nv_bfloat16* Atxth = ACh;
    const __nv_bfloat16* Atxtl = ACl;

    down_proj_bf_kernel<<<SIMG_, 256>>>(Aimgh, Aimgl, out_down, lrah, lral, INNER_);
    gemm_lr(Aimgh, Aimgl, Boh, Bol, lrah, lral, UToh, UTol, out_b,
            out_img, SIMG_, D_, INNER_);
    down_proj_bf_kernel<<<STXT_, 256>>>(Atxth, Atxtl, aout_down, lrbh, lrbl, INNER_);
    gemm_lr(Atxth, Atxtl, Baoh, Baol, lrbh, lrbl, UTaoh, UTaol, aout_b,
            out_txt, STXT_, D_, INNER_);
}

// round 14
// speedup vs baseline: 1.0084x; 1.0084x over previous
#include <cuda_runtime.h>
#include <cuda_bf16.h>
#include <math.h>
#include <stdint.h>

#define D_      3072
#define H_      24
#define HD_     128
#define R_      32
#define INNER_  3072
#define QKV3_   9216
#define SIMG_   1536
#define STXT_   512
#define SALL_   2048

// scale(1/sqrt(128)) * log2(e)
#define SCALE2E_ 0.12751743f

// ---------------- scratch (device globals; no runtime allocation) ----------
static __device__ float g_qkv_img[SIMG_ * QKV3_];
static __device__ float g_qkv_txt[STXT_ * QKV3_];

// low-rank intermediates, bf16 hi/lo
static __device__ __nv_bfloat16 g_lrah[SIMG_ * R_], g_lral[SIMG_ * R_];
static __device__ __nv_bfloat16 g_lrbh[STXT_ * R_], g_lrbl[STXT_ * R_];

// transposed up-projection matrices [N,32] bf16 hi/lo
static __device__ __nv_bfloat16 g_UTqh[QKV3_ * R_],  g_UTql[QKV3_ * R_];
static __device__ __nv_bfloat16 g_UTaqh[QKV3_ * R_], g_UTaql[QKV3_ * R_];
static __device__ __nv_bfloat16 g_UToh[D_ * R_],     g_UTol[D_ * R_];
static __device__ __nv_bfloat16 g_UTaoh[D_ * R_],    g_UTaol[D_ * R_];

// attention operands, bf16 hi/lo, layout [H][SALL][HD]
static __device__ __nv_bfloat16 g_qh[H_ * SALL_ * HD_], g_ql[H_ * SALL_ * HD_];
static __device__ __nv_bfloat16 g_kh[H_ * SALL_ * HD_], g_kl[H_ * SALL_ * HD_];
static __device__ __nv_bfloat16 g_vh[H_ * SALL_ * HD_], g_vl[H_ * SALL_ * HD_];

// attention output, bf16 hi/lo, [SALL][INNER] (txt rows 0..511, img 512..2047)
static __device__ __nv_bfloat16 g_ACh[SALL_ * INNER_], g_ACl[SALL_ * INNER_];

// bf16 hi/lo split buffers for projection GEMM inputs
static __device__ __nv_bfloat16 g_Aih[SIMG_ * D_],  g_Ail[SIMG_ * D_];
static __device__ __nv_bfloat16 g_Ath[STXT_ * D_],  g_Atl[STXT_ * D_];
static __device__ __nv_bfloat16 g_Bqh[QKV3_ * D_],  g_Bql[QKV3_ * D_];
static __device__ __nv_bfloat16 g_Baqh[QKV3_ * D_], g_Baql[QKV3_ * D_];
static __device__ __nv_bfloat16 g_Boh[D_ * INNER_], g_Bol[D_ * INNER_];
static __device__ __nv_bfloat16 g_Baoh[D_ * INNER_], g_Baol[D_ * INNER_];

// ---------------------------------------------------------------------------
// fp32 -> bf16 hi/lo split
// ---------------------------------------------------------------------------
__global__ void __launch_bounds__(256) split_bf16_kernel(
    const float* __restrict__ X, __nv_bfloat16* __restrict__ Xh,
    __nv_bfloat16* __restrict__ Xl, int n4)
{
    int i = blockIdx.x * blockDim.x + threadIdx.x;
    if (i >= n4) return;
    float4 v = ((const float4*)X)[i];
    union { __nv_bfloat16 b[4]; uint2 u; } ph, pl;
    ph.b[0] = __float2bfloat16(v.x);
    ph.b[1] = __float2bfloat16(v.y);
    ph.b[2] = __float2bfloat16(v.z);
    ph.b[3] = __float2bfloat16(v.w);
    pl.b[0] = __float2bfloat16(v.x - __bfloat162float(ph.b[0]));
    pl.b[1] = __float2bfloat16(v.y - __bfloat162float(ph.b[1]));
    pl.b[2] = __float2bfloat16(v.z - __bfloat162float(ph.b[2]));
    pl.b[3] = __float2bfloat16(v.w - __bfloat162float(ph.b[3]));
    ((uint2*)Xh)[i] = ph.u;
    ((uint2*)Xl)[i] = pl.u;
}

// transpose + split: U[32,N] fp32 -> UT[N,32] bf16 hi/lo
__global__ void __launch_bounds__(256) tsplit_kernel(
    const float* __restrict__ U, __nv_bfloat16* __restrict__ UTh,
    __nv_bfloat16* __restrict__ UTl, int N)
{
    int idx = blockIdx.x * blockDim.x + threadIdx.x;   // idx = k*N + n
    if (idx >= 32 * N) return;
    int n = idx % N, k = idx / N;
    float v = U[idx];
    __nv_bfloat16 h = __float2bfloat16(v);
    UTh[(size_t)n * 32 + k] = h;
    UTl[(size_t)n * 32 + k] = __float2bfloat16(v - __bfloat162float(h));
}

// ---------------------------------------------------------------------------
// helpers
// ---------------------------------------------------------------------------
__device__ __forceinline__ uint32_t sptr(const void* p) {
    return (uint32_t)__cvta_generic_to_shared(p);
}
__device__ __forceinline__ void ldsm_x4(uint32_t* r, uint32_t a) {
    asm volatile("ldmatrix.sync.aligned.m8n8.x4.shared.b16 {%0,%1,%2,%3}, [%4];"
                 : "=r"(r[0]), "=r"(r[1]), "=r"(r[2]), "=r"(r[3]) : "r"(a));
}
__device__ __forceinline__ void ldsm_x4_t(uint32_t* r, uint32_t a) {
    asm volatile("ldmatrix.sync.aligned.m8n8.x4.trans.shared.b16 {%0,%1,%2,%3}, [%4];"
                 : "=r"(r[0]), "=r"(r[1]), "=r"(r[2]), "=r"(r[3]) : "r"(a));
}
__device__ __forceinline__ void mma_bf16(float* c, const uint32_t* a,
                                         uint32_t b0, uint32_t b1) {
    asm volatile(
        "mma.sync.aligned.m16n8k16.row.col.f32.bf16.bf16.f32 "
        "{%0,%1,%2,%3},{%4,%5,%6,%7},{%8,%9},{%0,%1,%2,%3};"
        : "+f"(c[0]), "+f"(c[1]), "+f"(c[2]), "+f"(c[3])
        : "r"(a[0]), "r"(a[1]), "r"(a[2]), "r"(a[3]), "r"(b0), "r"(b1));
}
__device__ __forceinline__ uint32_t packbf(float lo, float hi) {
    uint32_t r;
    asm("cvt.rn.bf16x2.f32 %0, %1, %2;" : "=r"(r) : "f"(hi), "f"(lo));
    return r;
}
__device__ __forceinline__ float lobf(uint32_t r) { return __uint_as_float(r << 16); }
__device__ __forceinline__ float hibf(uint32_t r) { return __uint_as_float(r & 0xffff0000u); }
__device__ __forceinline__ void cpa16(uint32_t d, const void* g) {
    asm volatile("cp.async.cg.shared.global [%0], [%1], 16;" :: "r"(d), "l"(g));
}

// ---------------------------------------------------------------------------
// GEMM with low-rank fold:
//   C[M,N] = A[M,K] @ B[N,K]^T + LR[M,32] @ UT[N,32]^T (+bias)
// bf16 hi/lo, 3-product. CTA tile 128x256, warp tile 64x64 (8 warps = 2M x 4N),
// k-chunk 32, 3-stage cp.async pipeline. grid (N/256, M/128).
// stage layout (bytes): [Ah 10240][Al 10240][Bh 20480][Bl 20480]
// ---------------------------------------------------------------------------
#define GSTAGE_ 61440
#define GEMM_SMEM_ (3 * GSTAGE_)

__global__ void __launch_bounds__(256, 1) gemm_mma2_kernel(
    const __nv_bfloat16* __restrict__ Ah, const __nv_bfloat16* __restrict__ Al,
    const __nv_bfloat16* __restrict__ Bh, const __nv_bfloat16* __restrict__ Bl,
    const __nv_bfloat16* __restrict__ LRh, const __nv_bfloat16* __restrict__ LRl,
    const __nv_bfloat16* __restrict__ UTh, const __nv_bfloat16* __restrict__ UTl,
    const float* __restrict__ bias, float* __restrict__ C,
    int M, int N, int K)
{
    extern __shared__ char gsm[];
    const int tid  = threadIdx.x;
    const int brow = blockIdx.y * 128;
    const int bcol = blockIdx.x * 256;
    const int warp = tid >> 5, lane = tid & 31;
    const int wm = (warp & 1) * 64;
    const int wn = (warp >> 1) * 64;

    const int lrow = tid >> 2;           // 0..63
    const int lseg = (tid & 3) * 8;      // half offset
    const int segb = (tid & 3) * 16;     // byte offset

    const int nkmain = K >> 5;
    const int nk = nkmain + 1;           // + low-rank chunk

    auto issue_chunk = [&](int c) {
        char* buf = gsm + (c % 3) * GSTAGE_;
        const __nv_bfloat16 *pa0, *pa1, *pb0, *pb1;
        int sA, sB, koff;
        if (c < nkmain) {
            pa0 = Ah; pa1 = Al; pb0 = Bh; pb1 = Bl;
            sA = K; sB = K; koff = c * 32;
        } else {
            pa0 = LRh; pa1 = LRl; pb0 = UTh; pb1 = UTl;
            sA = 32; sB = 32; koff = 0;
        }
        const uint32_t s0 = sptr(buf);
        // A: 128 rows x 2 halves, 2 segs per row per thread pass
#pragma unroll
        for (int j = 0; j < 2; j++) {
            int row = lrow + j * 64;
            int ro = row * 80 + segb;
            cpa16(s0 + ro,         pa0 + (size_t)(brow + row) * sA + koff + lseg);
            cpa16(s0 + 10240 + ro, pa1 + (size_t)(brow + row) * sA + koff + lseg);
        }
        // B: 256 rows x 2 halves
#pragma unroll
        for (int j = 0; j < 4; j++) {
            int row = lrow + j * 64;
            int ro = row * 80 + segb;
            cpa16(s0 + 20480 + ro, pb0 + (size_t)(bcol + row) * sB + koff + lseg);
            cpa16(s0 + 40960 + ro, pb1 + (size_t)(bcol + row) * sB + koff + lseg);
        }
        asm volatile("cp.async.commit_group;");
    };

    float acc[4][8][4];
#pragma unroll
    for (int i = 0; i < 4; i++)
#pragma unroll
        for (int j = 0; j < 8; j++)
#pragma unroll
            for (int e = 0; e < 4; e++) acc[i][j][e] = 0.f;

    const int qa = lane >> 3, ra = lane & 7;
    const int a_row = (qa & 1) * 8 + ra;
    const int a_col = (qa >> 1) * 8;
    const int b_row = (qa >> 1) * 8 + ra;
    const int b_col = (qa & 1) * 8;

    issue_chunk(0);
    issue_chunk(1);

    for (int c = 0; c < nk; c++) {
        if (c + 1 < nk) asm volatile("cp.async.wait_group 1;");
        else            asm volatile("cp.async.wait_group 0;");
        __syncthreads();

        __nv_bfloat16* sAh = (__nv_bfloat16*)(gsm + (c % 3) * GSTAGE_);
        __nv_bfloat16* sAl = sAh + 5120;
        __nv_bfloat16* sBh = sAh + 10240;
        __nv_bfloat16* sBl = sAh + 20480;

#pragma unroll
        for (int kb = 0; kb < 32; kb += 16) {
            uint32_t ah[4][4], al[4][4];
#pragma unroll
            for (int mf = 0; mf < 4; mf++) {
                int r = wm + mf * 16 + a_row;
                ldsm_x4(ah[mf], sptr(&sAh[r * 40 + kb + a_col]));
                ldsm_x4(al[mf], sptr(&sAl[r * 40 + kb + a_col]));
            }
            // B in two half-passes of 32 cols to bound live registers
#pragma unroll
            for (int ph = 0; ph < 2; ph++) {
                uint32_t bh[2][4], bl[2][4];
#pragma unroll
                for (int p = 0; p < 2; p++) {
                    int r = wn + (ph * 2 + p) * 16 + b_row;
                    ldsm_x4(bh[p], sptr(&sBh[r * 40 + kb + b_col]));
                    ldsm_x4(bl[p], sptr(&sBl[r * 40 + kb + b_col]));
                }
#pragma unroll
                for (int mf = 0; mf < 4; mf++)
#pragma unroll
                    for (int nfl = 0; nfl < 4; nfl++) {
                        const int p = nfl >> 1, o = (nfl & 1) * 2;
                        float* a = acc[mf][ph * 4 + nfl];
                        mma_bf16(a, ah[mf], bh[p][o], bh[p][o + 1]);
                        mma_bf16(a, ah[mf], bl[p][o], bl[p][o + 1]);
                        mma_bf16(a, al[mf], bh[p][o], bh[p][o + 1]);
                    }
            }
        }
        __syncthreads();
        if (c + 2 < nk) issue_chunk(c + 2);
    }

    const int g = lane >> 2, t = lane & 3;
#pragma unroll
    for (int mf = 0; mf < 4; mf++) {
        int r0 = brow + wm + mf * 16 + g;
#pragma unroll
        for (int nf = 0; nf < 8; nf++) {
            int col = bcol + wn + nf * 8 + t * 2;
            float b0 = 0.f, b1 = 0.f;
            if (bias) { b0 = bias[col]; b1 = bias[col + 1]; }
            float2 v0, v1;
            v0.x = acc[mf][nf][0] + b0; v0.y = acc[mf][nf][1] + b1;
            v1.x = acc[mf][nf][2] + b0; v1.y = acc[mf][nf][3] + b1;
            *(float2*)(C + (size_t)r0 * N + col)       = v0;
            *(float2*)(C + (size_t)(r0 + 8) * N + col) = v1;
        }
    }
}

// ---------------------------------------------------------------------------
// down-proj: C[M,32] = A[M,K] @ B[K,32], output bf16 hi/lo. fp32-input variant.
// ---------------------------------------------------------------------------
__global__ void __launch_bounds__(256) down_proj_f32_kernel(
    const float* __restrict__ A, const float* __restrict__ B,
    __nv_bfloat16* __restrict__ Ch, __nv_bfloat16* __restrict__ Cl, int K)
{
    const int m = blockIdx.x;
    const int c = threadIdx.x & 31;
    const int kc = threadIdx.x >> 5;
    const float* a = A + (size_t)m * K;
    const int kchunk = K >> 3;
    const int k0 = kc * kchunk;
    float s = 0.f;
    for (int k = k0; k < k0 + kchunk; k++)
        s += a[k] * B[k * R_ + c];
    __shared__ float red[256];
    red[threadIdx.x] = s;
    __syncthreads();
    if (kc == 0) {
        float t = s;
#pragma unroll
        for (int i = 1; i < 8; i++) t += red[i * 32 + c];
        __nv_bfloat16 h = __float2bfloat16(t);
        Ch[m * R_ + c] = h;
        Cl[m * R_ + c] = __float2bfloat16(t - __bfloat162float(h));
    }
}

// bf16 hi/lo-input variant
__global__ void __launch_bounds__(256) down_proj_bf_kernel(
    const __nv_bfloat16* __restrict__ Ah, const __nv_bfloat16* __restrict__ Al,
    const float* __restrict__ B,
    __nv_bfloat16* __restrict__ Ch, __nv_bfloat16* __restrict__ Cl, int K)
{
    const int m = blockIdx.x;
    const int c = threadIdx.x & 31;
    const int kc = threadIdx.x >> 5;
    const __nv_bfloat16* ah = Ah + (size_t)m * K;
    const __nv_bfloat16* al = Al + (size_t)m * K;
    const int kchunk = K >> 3;
    const int k0 = kc * kchunk;
    float s = 0.f;
    for (int k = k0; k < k0 + kchunk; k++)
        s += (__bfloat162float(ah[k]) + __bfloat162float(al[k])) * B[k * R_ + c];
    __shared__ float red[256];
    red[threadIdx.x] = s;
    __syncthreads();
    if (kc == 0) {
        float t = s;
#pragma unroll
        for (int i = 1; i < 8; i++) t += red[i * 32 + c];
        __nv_bfloat16 h = __float2bfloat16(t);
        Ch[m * R_ + c] = h;
        Cl[m * R_ + c] = __float2bfloat16(t - __bfloat162float(h));
    }
}

// ---------------------------------------------------------------------------
// QKV post: heads, RMSNorm, RoPE; writes bf16 hi/lo Q(scaled)/K/V to [H][S][HD]
// ---------------------------------------------------------------------------
__global__ void __launch_bounds__(128) qkv_post_kernel(
    const float* __restrict__ qkv, int pos_off,
    const float* __restrict__ wq, const float* __restrict__ wk,
    const float* __restrict__ rcos, const float* __restrict__ rsin,
    __nv_bfloat16* __restrict__ qh, __nv_bfloat16* __restrict__ ql,
    __nv_bfloat16* __restrict__ kh, __nv_bfloat16* __restrict__ kl,
    __nv_bfloat16* __restrict__ vh, __nv_bfloat16* __restrict__ vl)
{
    const int s = blockIdx.x;
    const int h = blockIdx.y;
    const int d = threadIdx.x;
    const float* row = qkv + (size_t)s * QKV3_ + h * HD_;
    float q = row[d];
    float k = row[INNER_ + d];
    float v = row[2 * INNER_ + d];

    __shared__ float sh[8];
    float sq = q * q, sk = k * k;
#pragma unroll
    for (int o = 16; o > 0; o >>= 1) {
        sq += __shfl_xor_sync(0xffffffffu, sq, o);
        sk += __shfl_xor_sync(0xffffffffu, sk, o);
    }
    int w = d >> 5;
    if ((d & 31) == 0) { sh[w] = sq; sh[4 + w] = sk; }
    __syncthreads();
    sq = sh[0] + sh[1] + sh[2] + sh[3];
    sk = sh[4] + sh[5] + sh[6] + sh[7];
    float rq = rsqrtf(sq * (1.f / HD_) + 1e-5f);
    float rk = rsqrtf(sk * (1.f / HD_) + 1e-5f);
    q = q * rq * wq[d];
    k = k * rk * wk[d];

    const int pos = pos_off + s;
    float c = rcos[pos * 64 + (d >> 1)];
    float sn = rsin[pos * 64 + (d >> 1)];
    float qo = __shfl_xor_sync(0xffffffffu, q, 1);
    float ko = __shfl_xor_sync(0xffffffffu, k, 1);
    float qr = (d & 1) ? (qo * sn + q * c) : (q * c - qo * sn);
    float kr = (d & 1) ? (ko * sn + k * c) : (k * c - ko * sn);

    qr *= SCALE2E_;

    size_t o = ((size_t)h * SALL_ + pos) * HD_ + d;
    __nv_bfloat16 hq = __float2bfloat16(qr);
    __nv_bfloat16 hk = __float2bfloat16(kr);
    __nv_bfloat16 hv = __float2bfloat16(v);
    qh[o] = hq; ql[o] = __float2bfloat16(qr - __bfloat162float(hq));
    kh[o] = hk; kl[o] = __float2bfloat16(kr - __bfloat162float(hk));
    vh[o] = hv; vl[o] = __float2bfloat16(v  - __bfloat162float(hv));
}

// ---------------------------------------------------------------------------
// Tensor-core flash attention (mma.sync). Epilogue writes bf16 hi/lo.
// ---------------------------------------------------------------------------
#define ALDA_ 136
#define ATTN_SMEM_ ((2 * 128 + 4 * 64) * ALDA_ * 2)

__global__ void __launch_bounds__(256, 1) attn_mma_kernel(
    const __nv_bfloat16* __restrict__ Qh, const __nv_bfloat16* __restrict__ Ql,
    const __nv_bfloat16* __restrict__ Kh, const __nv_bfloat16* __restrict__ Kl,
    const __nv_bfloat16* __restrict__ Vh, const __nv_bfloat16* __restrict__ Vl,
    __nv_bfloat16* __restrict__ Oh, __nv_bfloat16* __restrict__ Ol)
{
    extern __shared__ __nv_bfloat16 sbuf[];
    __nv_bfloat16* sQh = sbuf;
    __nv_bfloat16* sQl = sQh + 128 * ALDA_;
    __nv_bfloat16* sKh = sQl + 128 * ALDA_;
    __nv_bfloat16* sKl = sKh + 64 * ALDA_;
    __nv_bfloat16* sVh = sKl + 64 * ALDA_;
    __nv_bfloat16* sVl = sVh + 64 * ALDA_;

    const int head = blockIdx.y;
    const int q0 = blockIdx.x * 128;
    const int tid = threadIdx.x;
    const int warp = tid >> 5, lane = tid & 31;
    const size_t hbase = (size_t)head * SALL_ * HD_;

    {
        const uint4* gqh = (const uint4*)(Qh + hbase + (size_t)q0 * HD_);
        const uint4* gql = (const uint4*)(Ql + hbase + (size_t)q0 * HD_);
#pragma unroll
        for (int k = 0; k < 8; k++) {
            int i = tid + k * 256;
            int row = i >> 4, seg = i & 15;
            *(uint4*)&sQh[row * ALDA_ + seg * 8] = gqh[i];
            *(uint4*)&sQl[row * ALDA_ + seg * 8] = gql[i];
        }
    }

    float accO[16][4];
#pragma unroll
    for (int i = 0; i < 16; i++)
#pragma unroll
        for (int e = 0; e < 4; e++) accO[i][e] = 0.f;
    float m0 = -1e30f, m1 = -1e30f, l0 = 0.f, l1 = 0.f;

    const int qa = lane >> 3, ra = lane & 7;
    const int arow = warp * 16 + (qa & 1) * 8 + ra;
    const int acol = (qa >> 1) * 8;
    const int vrow = lane & 15;
    const int vcol = (lane >> 4) * 8;

    for (int kt = 0; kt < SALL_ / 64; kt++) {
        __syncthreads();
        {
            const size_t kvoff = hbase + (size_t)(kt * 64) * HD_;
            const uint4* gkh = (const uint4*)(Kh + kvoff);
            const uint4* gkl = (const uint4*)(Kl + kvoff);
            const uint4* gvh = (const uint4*)(Vh + kvoff);
            const uint4* gvl = (const uint4*)(Vl + kvoff);
#pragma unroll
            for (int k = 0; k < 4; k++) {
                int i = tid + k * 256;
                int row = i >> 4, seg = i & 15;
                int dst = row * ALDA_ + seg * 8;
                *(uint4*)&sKh[dst] = gkh[i];
                *(uint4*)&sKl[dst] = gkl[i];
                *(uint4*)&sVh[dst] = gvh[i];
                *(uint4*)&sVl[dst] = gvl[i];
            }
        }
        __syncthreads();

        float accS[8][4];
#pragma unroll
        for (int j = 0; j < 8; j++)
#pragma unroll
            for (int e = 0; e < 4; e++) accS[j][e] = 0.f;

#pragma unroll
        for (int kc = 0; kc < 8; kc++) {
            uint32_t ah[4], al[4];
            ldsm_x4(ah, sptr(&sQh[arow * ALDA_ + kc * 16 + acol]));
            ldsm_x4(al, sptr(&sQl[arow * ALDA_ + kc * 16 + acol]));
#pragma unroll
            for (int np = 0; np < 4; np++) {
                uint32_t bh[4], bl[4];
                int br = np * 16 + (qa & 1) * 8 + ra;
                ldsm_x4(bh, sptr(&sKh[br * ALDA_ + kc * 16 + acol]));
                ldsm_x4(bl, sptr(&sKl[br * ALDA_ + kc * 16 + acol]));
                mma_bf16(accS[2 * np],     ah, bh[0], bh[2]);
                mma_bf16(accS[2 * np],     ah, bl[0], bl[2]);
                mma_bf16(accS[2 * np],     al, bh[0], bh[2]);
                mma_bf16(accS[2 * np + 1], ah, bh[1], bh[3]);
                mma_bf16(accS[2 * np + 1], ah, bl[1], bl[3]);
                mma_bf16(accS[2 * np + 1], al, bh[1], bh[3]);
            }
        }

        float ml0 = -1e30f, ml1 = -1e30f;
#pragma unroll
        for (int j = 0; j < 8; j++) {
            ml0 = fmaxf(ml0, fmaxf(accS[j][0], accS[j][1]));
            ml1 = fmaxf(ml1, fmaxf(accS[j][2], accS[j][3]));
        }
#pragma unroll
        for (int o = 1; o < 4; o <<= 1) {
            ml0 = fmaxf(ml0, __shfl_xor_sync(0xffffffffu, ml0, o));
            ml1 = fmaxf(ml1, __shfl_xor_sync(0xffffffffu, ml1, o));
        }
        float mn0 = fmaxf(m0, ml0), mn1 = fmaxf(m1, ml1);
        float f0 = exp2f(m0 - mn0), f1 = exp2f(m1 - mn1);
        float s0 = 0.f, s1 = 0.f;
#pragma unroll
        for (int j = 0; j < 8; j++) {
            accS[j][0] = exp2f(accS[j][0] - mn0);
            accS[j][1] = exp2f(accS[j][1] - mn0);
            accS[j][2] = exp2f(accS[j][2] - mn1);
            accS[j][3] = exp2f(accS[j][3] - mn1);
            s0 += accS[j][0] + accS[j][1];
            s1 += accS[j][2] + accS[j][3];
        }
#pragma unroll
        for (int o = 1; o < 4; o <<= 1) {
            s0 += __shfl_xor_sync(0xffffffffu, s0, o);
            s1 += __shfl_xor_sync(0xffffffffu, s1, o);
        }
        l0 = l0 * f0 + s0; l1 = l1 * f1 + s1;
        m0 = mn0; m1 = mn1;
#pragma unroll
        for (int i = 0; i < 16; i++) {
            accO[i][0] *= f0; accO[i][1] *= f0;
            accO[i][2] *= f1; accO[i][3] *= f1;
        }

#pragma unroll
        for (int kc2 = 0; kc2 < 4; kc2++) {
            const int j0 = 2 * kc2, j1 = j0 + 1;
            uint32_t pah[4], pal[4];
            pah[0] = packbf(accS[j0][0], accS[j0][1]);
            pah[1] = packbf(accS[j0][2], accS[j0][3]);
            pah[2] = packbf(accS[j1][0], accS[j1][1]);
            pah[3] = packbf(accS[j1][2], accS[j1][3]);
            pal[0] = packbf(accS[j0][0] - lobf(pah[0]), accS[j0][1] - hibf(pah[0]));
            pal[1] = packbf(accS[j0][2] - lobf(pah[1]), accS[j0][3] - hibf(pah[1]));
            pal[2] = packbf(accS[j1][0] - lobf(pah[2]), accS[j1][1] - hibf(pah[2]));
            pal[3] = packbf(accS[j1][2] - lobf(pah[3]), accS[j1][3] - hibf(pah[3]));

            const int vr = kc2 * 16 + vrow;
#pragma unroll
            for (int np = 0; np < 8; np++) {
                uint32_t vbh[4], vbl[4];
                ldsm_x4_t(vbh, sptr(&sVh[vr * ALDA_ + np * 16 + vcol]));
                ldsm_x4_t(vbl, sptr(&sVl[vr * ALDA_ + np * 16 + vcol]));
                mma_bf16(accO[2 * np],     pah, vbh[0], vbh[1]);
                mma_bf16(accO[2 * np],     pah, vbl[0], vbl[1]);
                mma_bf16(accO[2 * np],     pal, vbh[0], vbh[1]);
                mma_bf16(accO[2 * np + 1], pah, vbh[2], vbh[3]);
                mma_bf16(accO[2 * np + 1], pah, vbl[2], vbl[3]);
                mma_bf16(accO[2 * np + 1], pal, vbh[2], vbh[3]);
            }
        }
    }

    // epilogue: normalize and emit bf16 hi/lo directly
    const float inv0 = 1.f / l0, inv1 = 1.f / l1;
    const int r0 = q0 + warp * 16 + (lane >> 2);
    const int cb = head * HD_ + (lane & 3) * 2;
#pragma unroll
    for (int nt = 0; nt < 16; nt++) {
        float x0 = accO[nt][0] * inv0, y0 = accO[nt][1] * inv0;
        float x1 = accO[nt][2] * inv1, y1 = accO[nt][3] * inv1;
        uint32_t h0 = packbf(x0, y0);
        uint32_t e0 = packbf(x0 - lobf(h0), y0 - hibf(h0));
        uint32_t h1 = packbf(x1, y1);
        uint32_t e1 = packbf(x1 - lobf(h1), y1 - hibf(h1));
        size_t o0 = (size_t)r0 * INNER_ + cb + nt * 8;
        size_t o1 = (size_t)(r0 + 8) * INNER_ + cb + nt * 8;
        *(uint32_t*)&Oh[o0] = h0;  *(uint32_t*)&Ol[o0] = e0;
        *(uint32_t*)&Oh[o1] = h1;  *(uint32_t*)&Ol[o1] = e1;
    }
}

// ---------------------------------------------------------------------------
static inline void split_launch(const float* X, __nv_bfloat16* h, __nv_bfloat16* l,
                                long long n)
{
    int n4 = (int)(n >> 2);
    split_bf16_kernel<<<(n4 + 255) / 256, 256>>>(X, h, l, n4);
}

static inline void gemm_lr(const __nv_bfloat16* Ah, const __nv_bfloat16* Al,
                           const __nv_bfloat16* Bh, const __nv_bfloat16* Bl,
                           const __nv_bfloat16* LRh, const __nv_bfloat16* LRl,
                           const __nv_bfloat16* UTh, const __nv_bfloat16* UTl,
                           const float* bias, float* C, int M, int N, int K)
{
    cudaFuncSetAttribute(gemm_mma2_kernel, cudaFuncAttributeMaxDynamicSharedMemorySize,
                         GEMM_SMEM_);
    gemm_mma2_kernel<<<dim3(N / 256, M / 128), 256, GEMM_SMEM_>>>(
        Ah, Al, Bh, Bl, LRh, LRl, UTh, UTl, bias, C, M, N, K);
}

extern "C" void kernel_launch(void* const* d_in, const int* in_sizes, int n_in,
                              void* d_out, int out_size)
{
    const float* hs        = (const float*)d_in[0];
    const float* ehs       = (const float*)d_in[1];
    const float* rcos      = (const float*)d_in[2];
    const float* rsin      = (const float*)d_in[3];
    const float* qkv_w     = (const float*)d_in[4];
    const float* qkv_down  = (const float*)d_in[5];
    const float* qkv_up    = (const float*)d_in[6];
    const float* aqkv_w    = (const float*)d_in[7];
    const float* aqkv_down = (const float*)d_in[8];
    const float* aqkv_up   = (const float*)d_in[9];
    const float* out_w     = (const float*)d_in[10];
    const float* out_down  = (const float*)d_in[11];
    const float* out_up    = (const float*)d_in[12];
    const float* out_b     = (const float*)d_in[13];
    const float* aout_w    = (const float*)d_in[14];
    const float* aout_down = (const float*)d_in[15];
    const float* aout_up   = (const float*)d_in[16];
    const float* aout_b    = (const float*)d_in[17];
    const float* nq        = (const float*)d_in[18];
    const float* nk        = (const float*)d_in[19];
    const float* naq       = (const float*)d_in[20];
    const float* nak       = (const float*)d_in[21];

    float *qkv_img, *qkv_txt;
    cudaGetSymbolAddress((void**)&qkv_img, g_qkv_img);
    cudaGetSymbolAddress((void**)&qkv_txt, g_qkv_txt);

    __nv_bfloat16 *lrah, *lral, *lrbh, *lrbl;
    cudaGetSymbolAddress((void**)&lrah, g_lrah);
    cudaGetSymbolAddress((void**)&lral, g_lral);
    cudaGetSymbolAddress((void**)&lrbh, g_lrbh);
    cudaGetSymbolAddress((void**)&lrbl, g_lrbl);

    __nv_bfloat16 *UTqh, *UTql, *UTaqh, *UTaql, *UToh, *UTol, *UTaoh, *UTaol;
    cudaGetSymbolAddress((void**)&UTqh, g_UTqh);
    cudaGetSymbolAddress((void**)&UTql, g_UTql);
    cudaGetSymbolAddress((void**)&UTaqh, g_UTaqh);
    cudaGetSymbolAddress((void**)&UTaql, g_UTaql);
    cudaGetSymbolAddress((void**)&UToh, g_UToh);
    cudaGetSymbolAddress((void**)&UTol, g_UTol);
    cudaGetSymbolAddress((void**)&UTaoh, g_UTaoh);
    cudaGetSymbolAddress((void**)&UTaol, g_UTaol);

    __nv_bfloat16 *qbh, *qbl, *kbh, *kbl, *vbh, *vbl, *ACh, *ACl;
    cudaGetSymbolAddress((void**)&qbh, g_qh);
    cudaGetSymbolAddress((void**)&qbl, g_ql);
    cudaGetSymbolAddress((void**)&kbh, g_kh);
    cudaGetSymbolAddress((void**)&kbl, g_kl);
    cudaGetSymbolAddress((void**)&vbh, g_vh);
    cudaGetSymbolAddress((void**)&vbl, g_vl);
    cudaGetSymbolAddress((void**)&ACh, g_ACh);
    cudaGetSymbolAddress((void**)&ACl, g_ACl);

    __nv_bfloat16 *Aih, *Ail, *Ath, *Atl;
    __nv_bfloat16 *Bqh, *Bql, *Baqh, *Baql, *Boh, *Bol, *Baoh, *Baol;
    cudaGetSymbolAddress((void**)&Aih, g_Aih);
    cudaGetSymbolAddress((void**)&Ail, g_Ail);
    cudaGetSymbolAddress((void**)&Ath, g_Ath);
    cudaGetSymbolAddress((void**)&Atl, g_Atl);
    cudaGetSymbolAddress((void**)&Bqh, g_Bqh);
    cudaGetSymbolAddress((void**)&Bql, g_Bql);
    cudaGetSymbolAddress((void**)&Baqh, g_Baqh);
    cudaGetSymbolAddress((void**)&Baql, g_Baql);
    cudaGetSymbolAddress((void**)&Boh, g_Boh);
    cudaGetSymbolAddress((void**)&Bol, g_Bol);
    cudaGetSymbolAddress((void**)&Baoh, g_Baoh);
    cudaGetSymbolAddress((void**)&Baol, g_Baol);

    float* out_img = (float*)d_out;
    float* out_txt = (float*)d_out + (size_t)SIMG_ * D_;

    // ---- conversions ----
    split_launch(hs,     Aih,  Ail,  (long long)SIMG_ * D_);
    split_launch(ehs,    Ath,  Atl,  (long long)STXT_ * D_);
    split_launch(qkv_w,  Bqh,  Bql,  (long long)QKV3_ * D_);
    split_launch(aqkv_w, Baqh, Baql, (long long)QKV3_ * D_);
    split_launch(out_w,  Boh,  Bol,  (long long)D_ * INNER_);
    split_launch(aout_w, Baoh, Baol, (long long)D_ * INNER_);
    tsplit_kernel<<<(32 * QKV3_ + 255) / 256, 256>>>(qkv_up,  UTqh,  UTql,  QKV3_);
    tsplit_kernel<<<(32 * QKV3_ + 255) / 256, 256>>>(aqkv_up, UTaqh, UTaql, QKV3_);
    tsplit_kernel<<<(32 * D_ + 255) / 256, 256>>>(out_up,  UToh,  UTol,  D_);
    tsplit_kernel<<<(32 * D_ + 255) / 256, 256>>>(aout_up, UTaoh, UTaol, D_);

    // ---- QKV projections (dense + low-rank folded into one GEMM) ----
    down_proj_f32_kernel<<<SIMG_, 256>>>(hs, qkv_down, lrah, lral, D_);
    gemm_lr(Aih, Ail, Bqh, Bql, lrah, lral, UTqh, UTql, nullptr,
            qkv_img, SIMG_, QKV3_, D_);
    down_proj_f32_kernel<<<STXT_, 256>>>(ehs, aqkv_down, lrbh, lrbl, D_);
    gemm_lr(Ath, Atl, Baqh, Baql, lrbh, lrbl, UTaqh, UTaql, nullptr,
            qkv_txt, STXT_, QKV3_, D_);

    // ---- heads + RMSNorm + RoPE -> bf16 hi/lo Q/K/V (txt first, then img) ----
    qkv_post_kernel<<<dim3(STXT_, H_), 128>>>(qkv_txt, 0, naq, nak, rcos, rsin,
                                              qbh, qbl, kbh, kbl, vbh, vbl);
    qkv_post_kernel<<<dim3(SIMG_, H_), 128>>>(qkv_img, STXT_, nq, nk, rcos, rsin,
                                              qbh, qbl, kbh, kbl, vbh, vbl);

    // ---- tensor-core attention (emits bf16 hi/lo activations) ----
    cudaFuncSetAttribute(attn_mma_kernel, cudaFuncAttributeMaxDynamicSharedMemorySize,
                         ATTN_SMEM_);
    attn_mma_kernel<<<dim3(SALL_ / 128, H_), 256, ATTN_SMEM_>>>(
        qbh, qbl, kbh, kbl, vbh, vbl, ACh, ACl);

    // ---- output projections ----
    const __nv_bfloat16* Aimgh = ACh + (size_t)STXT_ * INNER_;
    const __nv_bfloat16* Aimgl = ACl + (size_t)STXT_ * INNER_;
    const __nv_bfloat16* Atxth = ACh;
    const __nv_bfloat16* Atxtl = ACl;

    down_proj_bf_kernel<<<SIMG_, 256>>>(Aimgh, Aimgl, out_down, lrah, lral, INNER_);
    gemm_lr(Aimgh, Aimgl, Boh, Bol, lrah, lral, UToh, UTol, out_b,
            out_img, SIMG_, D_, INNER_);
    down_proj_bf_kernel<<<STXT_, 256>>>(Atxth, Atxtl, aout_down, lrbh, lrbl, INNER_);
    gemm_lr(Atxth, Atxtl, Baoh, Baol, lrbh, lrbl, UTaoh, UTaol, aout_b,
            out_txt, STXT_, D_, INNER_);
}

// round 15
// speedup vs baseline: 1.3722x; 1.3608x over previous
#include <cuda_runtime.h>
#include <cuda_fp16.h>
#include <math.h>
#include <stdint.h>

#define D_      3072
#define H_      24
#define HD_     128
#define R_      32
#define INNER_  3072
#define QKV3_   9216
#define SIMG_   1536
#define STXT_   512
#define SALL_   2048

// scale(1/sqrt(128)) * log2(e)
#define SCALE2E_ 0.12751743f

// ---------------- scratch (device globals; no runtime allocation) ----------
static __device__ float g_qkv_img[SIMG_ * QKV3_];
static __device__ float g_qkv_txt[STXT_ * QKV3_];

// low-rank intermediates, fp16 hi/lo
static __device__ __half g_lrah[SIMG_ * R_], g_lral[SIMG_ * R_];
static __device__ __half g_lrbh[STXT_ * R_], g_lrbl[STXT_ * R_];

// transposed up-projection matrices [N,32] fp16 (hi only)
static __device__ __half g_UTq[QKV3_ * R_];
static __device__ __half g_UTaq[QKV3_ * R_];
static __device__ __half g_UTo[D_ * R_];
static __device__ __half g_UTao[D_ * R_];

// attention operands, layout [H][SALL][HD]: Q hi/lo, K hi, V hi
static __device__ __half g_qh[H_ * SALL_ * HD_], g_ql[H_ * SALL_ * HD_];
static __device__ __half g_kh[H_ * SALL_ * HD_];
static __device__ __half g_vh[H_ * SALL_ * HD_];

// attention output, fp16 hi/lo, [SALL][INNER] (txt rows 0..511, img 512..2047)
static __device__ __half g_ACh[SALL_ * INNER_], g_ACl[SALL_ * INNER_];

// A-side (activation) fp16 hi/lo buffers
static __device__ __half g_Aih[SIMG_ * D_],  g_Ail[SIMG_ * D_];
static __device__ __half g_Ath[STXT_ * D_],  g_Atl[STXT_ * D_];
// B-side (weight) fp16 buffers (hi only)
static __device__ __half g_Bq[QKV3_ * D_];
static __device__ __half g_Baq[QKV3_ * D_];
static __device__ __half g_Bo[D_ * INNER_];
static __device__ __half g_Bao[D_ * INNER_];

// ---------------------------------------------------------------------------
// fp32 -> fp16 hi/lo split (activations)
// ---------------------------------------------------------------------------
__global__ void __launch_bounds__(256) split_f16_kernel(
    const float* __restrict__ X, __half* __restrict__ Xh,
    __half* __restrict__ Xl, int n4)
{
    int i = blockIdx.x * blockDim.x + threadIdx.x;
    if (i >= n4) return;
    float4 v = ((const float4*)X)[i];
    union { __half b[4]; uint2 u; } ph, pl;
    ph.b[0] = __float2half(v.x);
    ph.b[1] = __float2half(v.y);
    ph.b[2] = __float2half(v.z);
    ph.b[3] = __float2half(v.w);
    pl.b[0] = __float2half(v.x - __half2float(ph.b[0]));
    pl.b[1] = __float2half(v.y - __half2float(ph.b[1]));
    pl.b[2] = __float2half(v.z - __half2float(ph.b[2]));
    pl.b[3] = __float2half(v.w - __half2float(ph.b[3]));
    ((uint2*)Xh)[i] = ph.u;
    ((uint2*)Xl)[i] = pl.u;
}

// fp32 -> fp16 convert (weights, no residual)
__global__ void __launch_bounds__(256) conv_f16_kernel(
    const float* __restrict__ X, __half* __restrict__ Xh, int n4)
{
    int i = blockIdx.x * blockDim.x + threadIdx.x;
    if (i >= n4) return;
    float4 v = ((const float4*)X)[i];
    union { __half b[4]; uint2 u; } ph;
    ph.b[0] = __float2half(v.x);
    ph.b[1] = __float2half(v.y);
    ph.b[2] = __float2half(v.z);
    ph.b[3] = __float2half(v.w);
    ((uint2*)Xh)[i] = ph.u;
}

// transpose + convert: U[32,N] fp32 -> UT[N,32] fp16
__global__ void __launch_bounds__(256) tconv_kernel(
    const float* __restrict__ U, __half* __restrict__ UT, int N)
{
    int idx = blockIdx.x * blockDim.x + threadIdx.x;   // idx = k*N + n
    if (idx >= 32 * N) return;
    int n = idx % N, k = idx / N;
    UT[(size_t)n * 32 + k] = __float2half(U[idx]);
}

// ---------------------------------------------------------------------------
// helpers
// ---------------------------------------------------------------------------
__device__ __forceinline__ uint32_t sptr(const void* p) {
    return (uint32_t)__cvta_generic_to_shared(p);
}
__device__ __forceinline__ void ldsm_x4(uint32_t* r, uint32_t a) {
    asm volatile("ldmatrix.sync.aligned.m8n8.x4.shared.b16 {%0,%1,%2,%3}, [%4];"
                 : "=r"(r[0]), "=r"(r[1]), "=r"(r[2]), "=r"(r[3]) : "r"(a));
}
__device__ __forceinline__ void ldsm_x4_t(uint32_t* r, uint32_t a) {
    asm volatile("ldmatrix.sync.aligned.m8n8.x4.trans.shared.b16 {%0,%1,%2,%3}, [%4];"
                 : "=r"(r[0]), "=r"(r[1]), "=r"(r[2]), "=r"(r[3]) : "r"(a));
}
__device__ __forceinline__ void mma_f16(float* c, const uint32_t* a,
                                        uint32_t b0, uint32_t b1) {
    asm volatile(
        "mma.sync.aligned.m16n8k16.row.col.f32.f16.f16.f32 "
        "{%0,%1,%2,%3},{%4,%5,%6,%7},{%8,%9},{%0,%1,%2,%3};"
        : "+f"(c[0]), "+f"(c[1]), "+f"(c[2]), "+f"(c[3])
        : "r"(a[0]), "r"(a[1]), "r"(a[2]), "r"(a[3]), "r"(b0), "r"(b1));
}
__device__ __forceinline__ uint32_t packh2(float lo, float hi) {
    uint32_t r;
    asm("cvt.rn.f16x2.f32 %0, %1, %2;" : "=r"(r) : "f"(hi), "f"(lo));
    return r;
}
__device__ __forceinline__ float lo16f(uint32_t r) {
    __half2 h = *reinterpret_cast<__half2*>(&r);
    return __low2float(h);
}
__device__ __forceinline__ float hi16f(uint32_t r) {
    __half2 h = *reinterpret_cast<__half2*>(&r);
    return __high2float(h);
}
__device__ __forceinline__ void cpa16(uint32_t d, const void* g) {
    asm volatile("cp.async.cg.shared.global [%0], [%1], 16;" :: "r"(d), "l"(g));
}

// ---------------------------------------------------------------------------
// GEMM, fp16 2-product (A hi/lo x B hi) with low-rank fold:
//   C[M,N] = (Ah+Al)[M,K] @ Bh[N,K]^T + (LRh+LRl)[M,32] @ UT[N,32]^T (+bias)
// CTA tile 128x256, warp tile 64x64 (8 warps = 2M x 4N), k-chunk 32,
// 3-stage cp.async pipeline. grid (N/256, M/128).
// stage layout (bytes): [Ah 10240][Al 10240][Bh 20480]
// ---------------------------------------------------------------------------
#define GSTAGE_ 40960
#define GEMM_SMEM_ (3 * GSTAGE_)

__global__ void __launch_bounds__(256, 1) gemm_mma2_kernel(
    const __half* __restrict__ Ah, const __half* __restrict__ Al,
    const __half* __restrict__ Bh,
    const __half* __restrict__ LRh, const __half* __restrict__ LRl,
    const __half* __restrict__ UT,
    const float* __restrict__ bias, float* __restrict__ C,
    int M, int N, int K)
{
    extern __shared__ char gsm[];
    const int tid  = threadIdx.x;
    const int brow = blockIdx.y * 128;
    const int bcol = blockIdx.x * 256;
    const int warp = tid >> 5, lane = tid & 31;
    const int wm = (warp & 1) * 64;
    const int wn = (warp >> 1) * 64;

    const int lrow = tid >> 2;           // 0..63
    const int lseg = (tid & 3) * 8;      // half offset
    const int segb = (tid & 3) * 16;     // byte offset

    const int nkmain = K >> 5;
    const int nk = nkmain + 1;           // + low-rank chunk

    auto issue_chunk = [&](int c) {
        char* buf = gsm + (c % 3) * GSTAGE_;
        const __half *pa0, *pa1, *pb0;
        int sA, sB, koff;
        if (c < nkmain) {
            pa0 = Ah; pa1 = Al; pb0 = Bh;
            sA = K; sB = K; koff = c * 32;
        } else {
            pa0 = LRh; pa1 = LRl; pb0 = UT;
            sA = 32; sB = 32; koff = 0;
        }
        const uint32_t s0 = sptr(buf);
        // A: 128 rows x 2 halves
#pragma unroll
        for (int j = 0; j < 2; j++) {
            int row = lrow + j * 64;
            int ro = row * 80 + segb;
            cpa16(s0 + ro,         pa0 + (size_t)(brow + row) * sA + koff + lseg);
            cpa16(s0 + 10240 + ro, pa1 + (size_t)(brow + row) * sA + koff + lseg);
        }
        // B: 256 rows, hi only
#pragma unroll
        for (int j = 0; j < 4; j++) {
            int row = lrow + j * 64;
            int ro = row * 80 + segb;
            cpa16(s0 + 20480 + ro, pb0 + (size_t)(bcol + row) * sB + koff + lseg);
        }
        asm volatile("cp.async.commit_group;");
    };

    float acc[4][8][4];
#pragma unroll
    for (int i = 0; i < 4; i++)
#pragma unroll
        for (int j = 0; j < 8; j++)
#pragma unroll
            for (int e = 0; e < 4; e++) acc[i][j][e] = 0.f;

    const int qa = lane >> 3, ra = lane & 7;
    const int a_row = (qa & 1) * 8 + ra;
    const int a_col = (qa >> 1) * 8;
    const int b_row = (qa >> 1) * 8 + ra;
    const int b_col = (qa & 1) * 8;

    issue_chunk(0);
    issue_chunk(1);

    for (int c = 0; c < nk; c++) {
        if (c + 1 < nk) asm volatile("cp.async.wait_group 1;");
        else            asm volatile("cp.async.wait_group 0;");
        __syncthreads();

        __half* sAh = (__half*)(gsm + (c % 3) * GSTAGE_);
        __half* sAl = sAh + 5120;
        __half* sBh = sAh + 10240;

#pragma unroll
        for (int kb = 0; kb < 32; kb += 16) {
            uint32_t ah[4][4], al[4][4];
#pragma unroll
            for (int mf = 0; mf < 4; mf++) {
                int r = wm + mf * 16 + a_row;
                ldsm_x4(ah[mf], sptr(&sAh[r * 40 + kb + a_col]));
                ldsm_x4(al[mf], sptr(&sAl[r * 40 + kb + a_col]));
            }
#pragma unroll
            for (int ph = 0; ph < 2; ph++) {
                uint32_t bh[2][4];
#pragma unroll
                for (int p = 0; p < 2; p++) {
                    int r = wn + (ph * 2 + p) * 16 + b_row;
                    ldsm_x4(bh[p], sptr(&sBh[r * 40 + kb + b_col]));
                }
#pragma unroll
                for (int mf = 0; mf < 4; mf++)
#pragma unroll
                    for (int nfl = 0; nfl < 4; nfl++) {
                        const int p = nfl >> 1, o = (nfl & 1) * 2;
                        float* a = acc[mf][ph * 4 + nfl];
                        mma_f16(a, ah[mf], bh[p][o], bh[p][o + 1]);
                        mma_f16(a, al[mf], bh[p][o], bh[p][o + 1]);
                    }
            }
        }
        __syncthreads();
        if (c + 2 < nk) issue_chunk(c + 2);
    }

    const int g = lane >> 2, t = lane & 3;
#pragma unroll
    for (int mf = 0; mf < 4; mf++) {
        int r0 = brow + wm + mf * 16 + g;
#pragma unroll
        for (int nf = 0; nf < 8; nf++) {
            int col = bcol + wn + nf * 8 + t * 2;
            float b0 = 0.f, b1 = 0.f;
            if (bias) { b0 = bias[col]; b1 = bias[col + 1]; }
            float2 v0, v1;
            v0.x = acc[mf][nf][0] + b0; v0.y = acc[mf][nf][1] + b1;
            v1.x = acc[mf][nf][2] + b0; v1.y = acc[mf][nf][3] + b1;
            *(float2*)(C + (size_t)r0 * N + col)       = v0;
            *(float2*)(C + (size_t)(r0 + 8) * N + col) = v1;
        }
    }
}

// ---------------------------------------------------------------------------
// down-proj: C[M,32] = A[M,K] @ B[K,32], output fp16 hi/lo. fp32-input variant.
// ---------------------------------------------------------------------------
__global__ void __launch_bounds__(256) down_proj_f32_kernel(
    const float* __restrict__ A, const float* __restrict__ B,
    __half* __restrict__ Ch, __half* __restrict__ Cl, int K)
{
    const int m = blockIdx.x;
    const int c = threadIdx.x & 31;
    const int kc = threadIdx.x >> 5;
    const float* a = A + (size_t)m * K;
    const int kchunk = K >> 3;
    const int k0 = kc * kchunk;
    float s = 0.f;
    for (int k = k0; k < k0 + kchunk; k++)
        s += a[k] * B[k * R_ + c];
    __shared__ float red[256];
    red[threadIdx.x] = s;
    __syncthreads();
    if (kc == 0) {
        float t = s;
#pragma unroll
        for (int i = 1; i < 8; i++) t += red[i * 32 + c];
        __half h = __float2half(t);
        Ch[m * R_ + c] = h;
        Cl[m * R_ + c] = __float2half(t - __half2float(h));
    }
}

// fp16 hi/lo-input variant
__global__ void __launch_bounds__(256) down_proj_hf_kernel(
    const __half* __restrict__ Ah, const __half* __restrict__ Al,
    const float* __restrict__ B,
    __half* __restrict__ Ch, __half* __restrict__ Cl, int K)
{
    const int m = blockIdx.x;
    const int c = threadIdx.x & 31;
    const int kc = threadIdx.x >> 5;
    const __half* ah = Ah + (size_t)m * K;
    const __half* al = Al + (size_t)m * K;
    const int kchunk = K >> 3;
    const int k0 = kc * kchunk;
    float s = 0.f;
    for (int k = k0; k < k0 + kchunk; k++)
        s += (__half2float(ah[k]) + __half2float(al[k])) * B[k * R_ + c];
    __shared__ float red[256];
    red[threadIdx.x] = s;
    __syncthreads();
    if (kc == 0) {
        float t = s;
#pragma unroll
        for (int i = 1; i < 8; i++) t += red[i * 32 + c];
        __half h = __float2half(t);
        Ch[m * R_ + c] = h;
        Cl[m * R_ + c] = __float2half(t - __half2float(h));
    }
}

// ---------------------------------------------------------------------------
// QKV post: heads, RMSNorm, RoPE; writes Q hi/lo (scaled), K hi, V hi
// ---------------------------------------------------------------------------
__global__ void __launch_bounds__(128) qkv_post_kernel(
    const float* __restrict__ qkv, int pos_off,
    const float* __restrict__ wq, const float* __restrict__ wk,
    const float* __restrict__ rcos, const float* __restrict__ rsin,
    __half* __restrict__ qh, __half* __restrict__ ql,
    __half* __restrict__ kh, __half* __restrict__ vh)
{
    const int s = blockIdx.x;
    const int h = blockIdx.y;
    const int d = threadIdx.x;
    const float* row = qkv + (size_t)s * QKV3_ + h * HD_;
    float q = row[d];
    float k = row[INNER_ + d];
    float v = row[2 * INNER_ + d];

    __shared__ float sh[8];
    float sq = q * q, sk = k * k;
#pragma unroll
    for (int o = 16; o > 0; o >>= 1) {
        sq += __shfl_xor_sync(0xffffffffu, sq, o);
        sk += __shfl_xor_sync(0xffffffffu, sk, o);
    }
    int w = d >> 5;
    if ((d & 31) == 0) { sh[w] = sq; sh[4 + w] = sk; }
    __syncthreads();
    sq = sh[0] + sh[1] + sh[2] + sh[3];
    sk = sh[4] + sh[5] + sh[6] + sh[7];
    float rq = rsqrtf(sq * (1.f / HD_) + 1e-5f);
    float rk = rsqrtf(sk * (1.f / HD_) + 1e-5f);
    q = q * rq * wq[d];
    k = k * rk * wk[d];

    const int pos = pos_off + s;
    float c = rcos[pos * 64 + (d >> 1)];
    float sn = rsin[pos * 64 + (d >> 1)];
    float qo = __shfl_xor_sync(0xffffffffu, q, 1);
    float ko = __shfl_xor_sync(0xffffffffu, k, 1);
    float qr = (d & 1) ? (qo * sn + q * c) : (q * c - qo * sn);
    float kr = (d & 1) ? (ko * sn + k * c) : (k * c - ko * sn);

    qr *= SCALE2E_;

    size_t o = ((size_t)h * SALL_ + pos) * HD_ + d;
    __half hq = __float2half(qr);
    qh[o] = hq;
    ql[o] = __float2half(qr - __half2float(hq));
    kh[o] = __float2half(kr);
    vh[o] = __float2half(v);
}

// ---------------------------------------------------------------------------
// Tensor-core flash attention, fp16 2-product (Q hi/lo x K hi; P hi/lo x V hi).
// Epilogue writes fp16 hi/lo.
// ---------------------------------------------------------------------------
#define ALDA_ 136
#define ATTN_SMEM_ ((2 * 128 + 2 * 64) * ALDA_ * 2)

__global__ void __launch_bounds__(256, 1) attn_mma_kernel(
    const __half* __restrict__ Qh, const __half* __restrict__ Ql,
    const __half* __restrict__ Kh, const __half* __restrict__ Vh,
    __half* __restrict__ Oh, __half* __restrict__ Ol)
{
    extern __shared__ __half sbuf[];
    __half* sQh = sbuf;
    __half* sQl = sQh + 128 * ALDA_;
    __half* sKh = sQl + 128 * ALDA_;
    __half* sVh = sKh + 64 * ALDA_;

    const int head = blockIdx.y;
    const int q0 = blockIdx.x * 128;
    const int tid = threadIdx.x;
    const int warp = tid >> 5, lane = tid & 31;
    const size_t hbase = (size_t)head * SALL_ * HD_;

    {
        const uint4* gqh = (const uint4*)(Qh + hbase + (size_t)q0 * HD_);
        const uint4* gql = (const uint4*)(Ql + hbase + (size_t)q0 * HD_);
#pragma unroll
        for (int k = 0; k < 8; k++) {
            int i = tid + k * 256;
            int row = i >> 4, seg = i & 15;
            *(uint4*)&sQh[row * ALDA_ + seg * 8] = gqh[i];
            *(uint4*)&sQl[row * ALDA_ + seg * 8] = gql[i];
        }
    }

    float accO[16][4];
#pragma unroll
    for (int i = 0; i < 16; i++)
#pragma unroll
        for (int e = 0; e < 4; e++) accO[i][e] = 0.f;
    float m0 = -1e30f, m1 = -1e30f, l0 = 0.f, l1 = 0.f;

    const int qa = lane >> 3, ra = lane & 7;
    const int arow = warp * 16 + (qa & 1) * 8 + ra;
    const int acol = (qa >> 1) * 8;
    const int vrow = lane & 15;
    const int vcol = (lane >> 4) * 8;

    for (int kt = 0; kt < SALL_ / 64; kt++) {
        __syncthreads();
        {
            const size_t kvoff = hbase + (size_t)(kt * 64) * HD_;
            const uint4* gkh = (const uint4*)(Kh + kvoff);
            const uint4* gvh = (const uint4*)(Vh + kvoff);
#pragma unroll
            for (int k = 0; k < 4; k++) {
                int i = tid + k * 256;
                int row = i >> 4, seg = i & 15;
                int dst = row * ALDA_ + seg * 8;
                *(uint4*)&sKh[dst] = gkh[i];
                *(uint4*)&sVh[dst] = gvh[i];
            }
        }
        __syncthreads();

        float accS[8][4];
#pragma unroll
        for (int j = 0; j < 8; j++)
#pragma unroll
            for (int e = 0; e < 4; e++) accS[j][e] = 0.f;

#pragma unroll
        for (int kc = 0; kc < 8; kc++) {
            uint32_t ah[4], al[4];
            ldsm_x4(ah, sptr(&sQh[arow * ALDA_ + kc * 16 + acol]));
            ldsm_x4(al, sptr(&sQl[arow * ALDA_ + kc * 16 + acol]));
#pragma unroll
            for (int np = 0; np < 4; np++) {
                uint32_t bh[4];
                int br = np * 16 + (qa & 1) * 8 + ra;
                ldsm_x4(bh, sptr(&sKh[br * ALDA_ + kc * 16 + acol]));
                mma_f16(accS[2 * np],     ah, bh[0], bh[2]);
                mma_f16(accS[2 * np],     al, bh[0], bh[2]);
                mma_f16(accS[2 * np + 1], ah, bh[1], bh[3]);
                mma_f16(accS[2 * np + 1], al, bh[1], bh[3]);
            }
        }

        float ml0 = -1e30f, ml1 = -1e30f;
#pragma unroll
        for (int j = 0; j < 8; j++) {
            ml0 = fmaxf(ml0, fmaxf(accS[j][0], accS[j][1]));
            ml1 = fmaxf(ml1, fmaxf(accS[j][2], accS[j][3]));
        }
#pragma unroll
        for (int o = 1; o < 4; o <<= 1) {
            ml0 = fmaxf(ml0, __shfl_xor_sync(0xffffffffu, ml0, o));
            ml1 = fmaxf(ml1, __shfl_xor_sync(0xffffffffu, ml1, o));
        }
        float mn0 = fmaxf(m0, ml0), mn1 = fmaxf(m1, ml1);
        float f0 = exp2f(m0 - mn0), f1 = exp2f(m1 - mn1);
        float s0 = 0.f, s1 = 0.f;
#pragma unroll
        for (int j = 0; j < 8; j++) {
            accS[j][0] = exp2f(accS[j][0] - mn0);
            accS[j][1] = exp2f(accS[j][1] - mn0);
            accS[j][2] = exp2f(accS[j][2] - mn1);
            accS[j][3] = exp2f(accS[j][3] - mn1);
            s0 += accS[j][0] + accS[j][1];
            s1 += accS[j][2] + accS[j][3];
        }
#pragma unroll
        for (int o = 1; o < 4; o <<= 1) {
            s0 += __shfl_xor_sync(0xffffffffu, s0, o);
            s1 += __shfl_xor_sync(0xffffffffu, s1, o);
        }
        l0 = l0 * f0 + s0; l1 = l1 * f1 + s1;
        m0 = mn0; m1 = mn1;
#pragma unroll
        for (int i = 0; i < 16; i++) {
            accO[i][0] *= f0; accO[i][1] *= f0;
            accO[i][2] *= f1; accO[i][3] *= f1;
        }

#pragma unroll
        for (int kc2 = 0; kc2 < 4; kc2++) {
            const int j0 = 2 * kc2, j1 = j0 + 1;
            uint32_t pah[4], pal[4];
            pah[0] = packh2(accS[j0][0], accS[j0][1]);
            pah[1] = packh2(accS[j0][2], accS[j0][3]);
            pah[2] = packh2(accS[j1][0], accS[j1][1]);
            pah[3] = packh2(accS[j1][2], accS[j1][3]);
            pal[0] = packh2(accS[j0][0] - lo16f(pah[0]), accS[j0][1] - hi16f(pah[0]));
            pal[1] = packh2(accS[j0][2] - lo16f(pah[1]), accS[j0][3] - hi16f(pah[1]));
            pal[2] = packh2(accS[j1][0] - lo16f(pah[2]), accS[j1][1] - hi16f(pah[2]));
            pal[3] = packh2(accS[j1][2] - lo16f(pah[3]), accS[j1][3] - hi16f(pah[3]));

            const int vr = kc2 * 16 + vrow;
#pragma unroll
            for (int np = 0; np < 8; np++) {
                uint32_t vbh[4];
                ldsm_x4_t(vbh, sptr(&sVh[vr * ALDA_ + np * 16 + vcol]));
                mma_f16(accO[2 * np],     pah, vbh[0], vbh[1]);
                mma_f16(accO[2 * np],     pal, vbh[0], vbh[1]);
                mma_f16(accO[2 * np + 1], pah, vbh[2], vbh[3]);
                mma_f16(accO[2 * np + 1], pal, vbh[2], vbh[3]);
            }
        }
    }

    // epilogue: normalize and emit fp16 hi/lo directly
    const float inv0 = 1.f / l0, inv1 = 1.f / l1;
    const int r0 = q0 + warp * 16 + (lane >> 2);
    const int cb = head * HD_ + (lane & 3) * 2;
#pragma unroll
    for (int nt = 0; nt < 16; nt++) {
        float x0 = accO[nt][0] * inv0, y0 = accO[nt][1] * inv0;
        float x1 = accO[nt][2] * inv1, y1 = accO[nt][3] * inv1;
        uint32_t h0 = packh2(x0, y0);
        uint32_t e0 = packh2(x0 - lo16f(h0), y0 - hi16f(h0));
        uint32_t h1 = packh2(x1, y1);
        uint32_t e1 = packh2(x1 - lo16f(h1), y1 - hi16f(h1));
        size_t o0 = (size_t)r0 * INNER_ + cb + nt * 8;
        size_t o1 = (size_t)(r0 + 8) * INNER_ + cb + nt * 8;
        *(uint32_t*)&Oh[o0] = h0;  *(uint32_t*)&Ol[o0] = e0;
        *(uint32_t*)&Oh[o1] = h1;  *(uint32_t*)&Ol[o1] = e1;
    }
}

// ---------------------------------------------------------------------------
static inline void split_launch(const float* X, __half* h, __half* l, long long n)
{
    int n4 = (int)(n >> 2);
    split_f16_kernel<<<(n4 + 255) / 256, 256>>>(X, h, l, n4);
}
static inline void conv_launch(const float* X, __half* h, long long n)
{
    int n4 = (int)(n >> 2);
    conv_f16_kernel<<<(n4 + 255) / 256, 256>>>(X, h, n4);
}

static inline void gemm_lr(const __half* Ah, const __half* Al, const __half* Bh,
                           const __half* LRh, const __half* LRl, const __half* UT,
                           const float* bias, float* C, int M, int N, int K)
{
    cudaFuncSetAttribute(gemm_mma2_kernel, cudaFuncAttributeMaxDynamicSharedMemorySize,
                         GEMM_SMEM_);
    gemm_mma2_kernel<<<dim3(N / 256, M / 128), 256, GEMM_SMEM_>>>(
        Ah, Al, Bh, LRh, LRl, UT, bias, C, M, N, K);
}

extern "C" void kernel_launch(void* const* d_in, const int* in_sizes, int n_in,
                              void* d_out, int out_size)
{
    const float* hs        = (const float*)d_in[0];
    const float* ehs       = (const float*)d_in[1];
    const float* rcos      = (const float*)d_in[2];
    const float* rsin      = (const float*)d_in[3];
    const float* qkv_w     = (const float*)d_in[4];
    const float* qkv_down  = (const float*)d_in[5];
    const float* qkv_up    = (const float*)d_in[6];
    const float* aqkv_w    = (const float*)d_in[7];
    const float* aqkv_down = (const float*)d_in[8];
    const float* aqkv_up   = (const float*)d_in[9];
    const float* out_w     = (const float*)d_in[10];
    const float* out_down  = (const float*)d_in[11];
    const float* out_up    = (const float*)d_in[12];
    const float* out_b     = (const float*)d_in[13];
    const float* aout_w    = (const float*)d_in[14];
    const float* aout_down = (const float*)d_in[15];
    const float* aout_up   = (const float*)d_in[16];
    const float* aout_b    = (const float*)d_in[17];
    const float* nq        = (const float*)d_in[18];
    const float* nk        = (const float*)d_in[19];
    const float* naq       = (const float*)d_in[20];
    const float* nak       = (const float*)d_in[21];

    float *qkv_img, *qkv_txt;
    cudaGetSymbolAddress((void**)&qkv_img, g_qkv_img);
    cudaGetSymbolAddress((void**)&qkv_txt, g_qkv_txt);

    __half *lrah, *lral, *lrbh, *lrbl;
    cudaGetSymbolAddress((void**)&lrah, g_lrah);
    cudaGetSymbolAddress((void**)&lral, g_lral);
    cudaGetSymbolAddress((void**)&lrbh, g_lrbh);
    cudaGetSymbolAddress((void**)&lrbl, g_lrbl);

    __half *UTq, *UTaq, *UTo, *UTao;
    cudaGetSymbolAddress((void**)&UTq, g_UTq);
    cudaGetSymbolAddress((void**)&UTaq, g_UTaq);
    cudaGetSymbolAddress((void**)&UTo, g_UTo);
    cudaGetSymbolAddress((void**)&UTao, g_UTao);

    __half *qbh, *qbl, *kbh, *vbh, *ACh, *ACl;
    cudaGetSymbolAddress((void**)&qbh, g_qh);
    cudaGetSymbolAddress((void**)&qbl, g_ql);
    cudaGetSymbolAddress((void**)&kbh, g_kh);
    cudaGetSymbolAddress((void**)&vbh, g_vh);
    cudaGetSymbolAddress((void**)&ACh, g_ACh);
    cudaGetSymbolAddress((void**)&ACl, g_ACl);

    __half *Aih, *Ail, *Ath, *Atl, *Bq, *Baq, *Bo, *Bao;
    cudaGetSymbolAddress((void**)&Aih, g_Aih);
    cudaGetSymbolAddress((void**)&Ail, g_Ail);
    cudaGetSymbolAddress((void**)&Ath, g_Ath);
    cudaGetSymbolAddress((void**)&Atl, g_Atl);
    cudaGetSymbolAddress((void**)&Bq, g_Bq);
    cudaGetSymbolAddress((void**)&Baq, g_Baq);
    cudaGetSymbolAddress((void**)&Bo, g_Bo);
    cudaGetSymbolAddress((void**)&Bao, g_Bao);

    float* out_img = (float*)d_out;
    float* out_txt = (float*)d_out + (size_t)SIMG_ * D_;

    // ---- conversions ----
    split_launch(hs,  Aih, Ail, (long long)SIMG_ * D_);
    split_launch(ehs, Ath, Atl, (long long)STXT_ * D_);
    conv_launch(qkv_w,  Bq,  (long long)QKV3_ * D_);
    conv_launch(aqkv_w, Baq, (long long)QKV3_ * D_);
    conv_launch(out_w,  Bo,  (long long)D_ * INNER_);
    conv_launch(aout_w, Bao, (long long)D_ * INNER_);
    tconv_kernel<<<(32 * QKV3_ + 255) / 256, 256>>>(qkv_up,  UTq,  QKV3_);
    tconv_kernel<<<(32 * QKV3_ + 255) / 256, 256>>>(aqkv_up, UTaq, QKV3_);
    tconv_kernel<<<(32 * D_ + 255) / 256, 256>>>(out_up,  UTo,  D_);
    tconv_kernel<<<(32 * D_ + 255) / 256, 256>>>(aout_up, UTao, D_);

    // ---- QKV projections (dense + low-rank folded into one GEMM) ----
    down_proj_f32_kernel<<<SIMG_, 256>>>(hs, qkv_down, lrah, lral, D_);
    gemm_lr(Aih, Ail, Bq, lrah, lral, UTq, nullptr, qkv_img, SIMG_, QKV3_, D_);
    down_proj_f32_kernel<<<STXT_, 256>>>(ehs, aqkv_down, lrbh, lrbl, D_);
    gemm_lr(Ath, Atl, Baq, lrbh, lrbl, UTaq, nullptr, qkv_txt, STXT_, QKV3_, D_);

    // ---- heads + RMSNorm + RoPE -> Q hi/lo, K hi, V hi (txt first, then img) ----
    qkv_post_kernel<<<dim3(STXT_, H_), 128>>>(qkv_txt, 0, naq, nak, rcos, rsin,
                                              qbh, qbl, kbh, vbh);
    qkv_post_kernel<<<dim3(SIMG_, H_), 128>>>(qkv_img, STXT_, nq, nk, rcos, rsin,
                                              qbh, qbl, kbh, vbh);

    // ---- tensor-core attention (emits fp16 hi/lo activations) ----
    cudaFuncSetAttribute(attn_mma_kernel, cudaFuncAttributeMaxDynamicSharedMemorySize,
                         ATTN_SMEM_);
    attn_mma_kernel<<<dim3(SALL_ / 128, H_), 256, ATTN_SMEM_>>>(
        qbh, qbl, kbh, vbh, ACh, ACl);

    // ---- output projections ----
    const __half* Aimgh = ACh + (size_t)STXT_ * INNER_;
    const __half* Aimgl = ACl + (size_t)STXT_ * INNER_;
    const __half* Atxth = ACh;
    const __half* Atxtl = ACl;

    down_proj_hf_kernel<<<SIMG_, 256>>>(Aimgh, Aimgl, out_down, lrah, lral, INNER_);
    gemm_lr(Aimgh, Aimgl, Bo, lrah, lral, UTo, out_b, out_img, SIMG_, D_, INNER_);
    down_proj_hf_kernel<<<STXT_, 256>>>(Atxth, Atxtl, aout_down, lrbh, lrbl, INNER_);
    gemm_lr(Atxth, Atxtl, Bao, lrbh, lrbl, UTao, aout_b, out_txt, STXT_, D_, INNER_);
}

// round 17
// speedup vs baseline: 1.6899x; 1.2315x over previous
#include <cuda_runtime.h>
#include <cuda_fp16.h>
#include <math.h>
#include <stdint.h>

#define D_      3072
#define H_      24
#define HD_     128
#define R_      32
#define INNER_  3072
#define QKV3_   9216
#define SIMG_   1536
#define STXT_   512
#define SALL_   2048

// scale(1/sqrt(128)) * log2(e)
#define SCALE2E_ 0.12751743f

// ---------------- scratch (device globals; no runtime allocation) ----------
static __device__ float g_qkv_img[SIMG_ * QKV3_];
static __device__ float g_qkv_txt[STXT_ * QKV3_];

// low-rank intermediates, fp16 hi/lo
static __device__ __half g_lrah[SIMG_ * R_], g_lral[SIMG_ * R_];
static __device__ __half g_lrbh[STXT_ * R_], g_lrbl[STXT_ * R_];

// transposed up-projection matrices [N,32] fp16
static __device__ __half g_UTq[QKV3_ * R_];
static __device__ __half g_UTaq[QKV3_ * R_];
static __device__ __half g_UTo[D_ * R_];
static __device__ __half g_UTao[D_ * R_];

// attention operands, layout [H][SALL][HD]: Q hi, K hi, V hi
static __device__ __half g_qh[H_ * SALL_ * HD_];
static __device__ __half g_kh[H_ * SALL_ * HD_];
static __device__ __half g_vh[H_ * SALL_ * HD_];

// attention output, fp16 hi/lo, [SALL][INNER] (txt rows 0..511, img 512..2047)
static __device__ __half g_ACh[SALL_ * INNER_], g_ACl[SALL_ * INNER_];

// activation fp16 buffers (hi only for QKV stage)
static __device__ __half g_Ai[SIMG_ * D_];
static __device__ __half g_At[STXT_ * D_];
// weight fp16 buffers
static __device__ __half g_Bq[QKV3_ * D_];
static __device__ __half g_Baq[QKV3_ * D_];
static __device__ __half g_Bo[D_ * INNER_];
static __device__ __half g_Bao[D_ * INNER_];

// ---------------------------------------------------------------------------
// fp32 -> fp16 convert
// ---------------------------------------------------------------------------
__global__ void __launch_bounds__(256) conv_f16_kernel(
    const float* __restrict__ X, __half* __restrict__ Xh, int n4)
{
    int i = blockIdx.x * blockDim.x + threadIdx.x;
    if (i >= n4) return;
    float4 v = ((const float4*)X)[i];
    union { __half b[4]; uint2 u; } ph;
    ph.b[0] = __float2half(v.x);
    ph.b[1] = __float2half(v.y);
    ph.b[2] = __float2half(v.z);
    ph.b[3] = __float2half(v.w);
    ((uint2*)Xh)[i] = ph.u;
}

// transpose + convert: U[32,N] fp32 -> UT[N,32] fp16
__global__ void __launch_bounds__(256) tconv_kernel(
    const float* __restrict__ U, __half* __restrict__ UT, int N)
{
    int idx = blockIdx.x * blockDim.x + threadIdx.x;   // idx = k*N + n
    if (idx >= 32 * N) return;
    int n = idx % N, k = idx / N;
    UT[(size_t)n * 32 + k] = __float2half(U[idx]);
}

// ---------------------------------------------------------------------------
// helpers
// ---------------------------------------------------------------------------
__device__ __forceinline__ uint32_t sptr(const void* p) {
    return (uint32_t)__cvta_generic_to_shared(p);
}
__device__ __forceinline__ void ldsm_x4(uint32_t* r, uint32_t a) {
    asm volatile("ldmatrix.sync.aligned.m8n8.x4.shared.b16 {%0,%1,%2,%3}, [%4];"
                 : "=r"(r[0]), "=r"(r[1]), "=r"(r[2]), "=r"(r[3]) : "r"(a));
}
__device__ __forceinline__ void ldsm_x4_t(uint32_t* r, uint32_t a) {
    asm volatile("ldmatrix.sync.aligned.m8n8.x4.trans.shared.b16 {%0,%1,%2,%3}, [%4];"
                 : "=r"(r[0]), "=r"(r[1]), "=r"(r[2]), "=r"(r[3]) : "r"(a));
}
__device__ __forceinline__ void mma_f16(float* c, const uint32_t* a,
                                        uint32_t b0, uint32_t b1) {
    asm volatile(
        "mma.sync.aligned.m16n8k16.row.col.f32.f16.f16.f32 "
        "{%0,%1,%2,%3},{%4,%5,%6,%7},{%8,%9},{%0,%1,%2,%3};"
        : "+f"(c[0]), "+f"(c[1]), "+f"(c[2]), "+f"(c[3])
        : "r"(a[0]), "r"(a[1]), "r"(a[2]), "r"(a[3]), "r"(b0), "r"(b1));
}
__device__ __forceinline__ uint32_t packh2(float lo, float hi) {
    uint32_t r;
    asm("cvt.rn.f16x2.f32 %0, %1, %2;" : "=r"(r) : "f"(hi), "f"(lo));
    return r;
}
__device__ __forceinline__ float lo16f(uint32_t r) {
    __half2 h = *reinterpret_cast<__half2*>(&r);
    return __low2float(h);
}
__device__ __forceinline__ float hi16f(uint32_t r) {
    __half2 h = *reinterpret_cast<__half2*>(&r);
    return __high2float(h);
}
__device__ __forceinline__ void cpa16(uint32_t d, const void* g) {
    asm volatile("cp.async.cg.shared.global [%0], [%1], 16;" :: "r"(d), "l"(g));
}

// ---------------------------------------------------------------------------
// GEMM, fp16, APROD products (1: Ah x Bh; 2: (Ah+Al) x Bh), low-rank fold:
//   C[M,N] = A[M,K] @ Bh[N,K]^T + LR[M,32] @ UT[N,32]^T (+bias)
// CTA tile 128x256, warp tile 64x64 (8 warps = 2M x 4N), k-chunk 32,
// 3-stage cp.async pipeline. grid (N/256, M/128).
// stage layout: [Ah 10240][(Al 10240 if APROD==2)][Bh 20480]
// ---------------------------------------------------------------------------
template<int APROD>
__global__ void __launch_bounds__(256, 1) gemm_mma2_kernel(
    const __half* __restrict__ Ah, const __half* __restrict__ Al,
    const __half* __restrict__ Bh,
    const __half* __restrict__ LRh, const __half* __restrict__ LRl,
    const __half* __restrict__ UT,
    const float* __restrict__ bias, float* __restrict__ C,
    int M, int N, int K)
{
    constexpr int GSTAGE = (APROD + 1) * 10240 + 10240;   // A tiles + B tile
    constexpr int BOFF = APROD * 10240;
    extern __shared__ char gsm[];
    const int tid  = threadIdx.x;
    const int brow = blockIdx.y * 128;
    const int bcol = blockIdx.x * 256;
    const int warp = tid >> 5, lane = tid & 31;
    const int wm = (warp & 1) * 64;
    const int wn = (warp >> 1) * 64;

    const int lrow = tid >> 2;           // 0..63
    const int lseg = (tid & 3) * 8;      // half offset
    const int segb = (tid & 3) * 16;     // byte offset

    const int nkmain = K >> 5;
    const int nk = nkmain + 1;           // + low-rank chunk

    auto issue_chunk = [&](int c) {
        char* buf = gsm + (c % 3) * GSTAGE;
        const __half *pa0, *pa1, *pb0;
        int sA, sB, koff;
        if (c < nkmain) {
            pa0 = Ah; pa1 = Al; pb0 = Bh;
            sA = K; sB = K; koff = c * 32;
        } else {
            pa0 = LRh; pa1 = LRl; pb0 = UT;
            sA = 32; sB = 32; koff = 0;
        }
        const uint32_t s0 = sptr(buf);
#pragma unroll
        for (int j = 0; j < 2; j++) {
            int row = lrow + j * 64;
            int ro = row * 80 + segb;
            cpa16(s0 + ro, pa0 + (size_t)(brow + row) * sA + koff + lseg);
            if (APROD == 2)
                cpa16(s0 + 10240 + ro, pa1 + (size_t)(brow + row) * sA + koff + lseg);
        }
#pragma unroll
        for (int j = 0; j < 4; j++) {
            int row = lrow + j * 64;
            int ro = row * 80 + segb;
            cpa16(s0 + BOFF + ro, pb0 + (size_t)(bcol + row) * sB + koff + lseg);
        }
        asm volatile("cp.async.commit_group;");
    };

    float acc[4][8][4];
#pragma unroll
    for (int i = 0; i < 4; i++)
#pragma unroll
        for (int j = 0; j < 8; j++)
#pragma unroll
            for (int e = 0; e < 4; e++) acc[i][j][e] = 0.f;

    const int qa = lane >> 3, ra = lane & 7;
    const int a_row = (qa & 1) * 8 + ra;
    const int a_col = (qa >> 1) * 8;
    const int b_row = (qa >> 1) * 8 + ra;
    const int b_col = (qa & 1) * 8;

    issue_chunk(0);
    issue_chunk(1);

    for (int c = 0; c < nk; c++) {
        if (c + 1 < nk) asm volatile("cp.async.wait_group 1;");
        else            asm volatile("cp.async.wait_group 0;");
        __syncthreads();

        __half* sAh = (__half*)(gsm + (c % 3) * GSTAGE);
        __half* sAl = sAh + 5120;
        __half* sBh = sAh + BOFF / 2;

#pragma unroll
        for (int kb = 0; kb < 32; kb += 16) {
            uint32_t ah[4][4], al[4][4];
#pragma unroll
            for (int mf = 0; mf < 4; mf++) {
                int r = wm + mf * 16 + a_row;
                ldsm_x4(ah[mf], sptr(&sAh[r * 40 + kb + a_col]));
                if (APROD == 2)
                    ldsm_x4(al[mf], sptr(&sAl[r * 40 + kb + a_col]));
            }
#pragma unroll
            for (int ph = 0; ph < 2; ph++) {
                uint32_t bh[2][4];
#pragma unroll
                for (int p = 0; p < 2; p++) {
                    int r = wn + (ph * 2 + p) * 16 + b_row;
                    ldsm_x4(bh[p], sptr(&sBh[r * 40 + kb + b_col]));
                }
#pragma unroll
                for (int mf = 0; mf < 4; mf++)
#pragma unroll
                    for (int nfl = 0; nfl < 4; nfl++) {
                        const int p = nfl >> 1, o = (nfl & 1) * 2;
                        float* a = acc[mf][ph * 4 + nfl];
                        mma_f16(a, ah[mf], bh[p][o], bh[p][o + 1]);
                        if (APROD == 2)
                            mma_f16(a, al[mf], bh[p][o], bh[p][o + 1]);
                    }
            }
        }
        __syncthreads();
        if (c + 2 < nk) issue_chunk(c + 2);
    }

    const int g = lane >> 2, t = lane & 3;
#pragma unroll
    for (int mf = 0; mf < 4; mf++) {
        int r0 = brow + wm + mf * 16 + g;
#pragma unroll
        for (int nf = 0; nf < 8; nf++) {
            int col = bcol + wn + nf * 8 + t * 2;
            float b0 = 0.f, b1 = 0.f;
            if (bias) { b0 = bias[col]; b1 = bias[col + 1]; }
            float2 v0, v1;
            v0.x = acc[mf][nf][0] + b0; v0.y = acc[mf][nf][1] + b1;
            v1.x = acc[mf][nf][2] + b0; v1.y = acc[mf][nf][3] + b1;
            *(float2*)(C + (size_t)r0 * N + col)       = v0;
            *(float2*)(C + (size_t)(r0 + 8) * N + col) = v1;
        }
    }
}

// ---------------------------------------------------------------------------
// down-proj: C[M,32] = A[M,K] @ B[K,32], output fp16 hi/lo. fp32-input variant.
// ---------------------------------------------------------------------------
__global__ void __launch_bounds__(256) down_proj_f32_kernel(
    const float* __restrict__ A, const float* __restrict__ B,
    __half* __restrict__ Ch, __half* __restrict__ Cl, int K)
{
    const int m = blockIdx.x;
    const int c = threadIdx.x & 31;
    const int kc = threadIdx.x >> 5;
    const float* a = A + (size_t)m * K;
    const int kchunk = K >> 3;
    const int k0 = kc * kchunk;
    float s = 0.f;
    for (int k = k0; k < k0 + kchunk; k++)
        s += a[k] * B[k * R_ + c];
    __shared__ float red[256];
    red[threadIdx.x] = s;
    __syncthreads();
    if (kc == 0) {
        float t = s;
#pragma unroll
        for (int i = 1; i < 8; i++) t += red[i * 32 + c];
        __half h = __float2half(t);
        Ch[m * R_ + c] = h;
        Cl[m * R_ + c] = __float2half(t - __half2float(h));
    }
}

// fp16 hi/lo-input variant
__global__ void __launch_bounds__(256) down_proj_hf_kernel(
    const __half* __restrict__ Ah, const __half* __restrict__ Al,
    const float* __restrict__ B,
    __half* __restrict__ Ch, __half* __restrict__ Cl, int K)
{
    const int m = blockIdx.x;
    const int c = threadIdx.x & 31;
    const int kc = threadIdx.x >> 5;
    const __half* ah = Ah + (size_t)m * K;
    const __half* al = Al + (size_t)m * K;
    const int kchunk = K >> 3;
    const int k0 = kc * kchunk;
    float s = 0.f;
    for (int k = k0; k < k0 + kchunk; k++)
        s += (__half2float(ah[k]) + __half2float(al[k])) * B[k * R_ + c];
    __shared__ float red[256];
    red[threadIdx.x] = s;
    __syncthreads();
    if (kc == 0) {
        float t = s;
#pragma unroll
        for (int i = 1; i < 8; i++) t += red[i * 32 + c];
        __half h = __float2half(t);
        Ch[m * R_ + c] = h;
        Cl[m * R_ + c] = __float2half(t - __half2float(h));
    }
}

// ---------------------------------------------------------------------------
// QKV post: heads, RMSNorm, RoPE; writes Q hi (scaled), K hi, V hi
// ---------------------------------------------------------------------------
__global__ void __launch_bounds__(128) qkv_post_kernel(
    const float* __restrict__ qkv, int pos_off,
    const float* __restrict__ wq, const float* __restrict__ wk,
    const float* __restrict__ rcos, const float* __restrict__ rsin,
    __half* __restrict__ qh, __half* __restrict__ kh, __half* __restrict__ vh)
{
    const int s = blockIdx.x;
    const int h = blockIdx.y;
    const int d = threadIdx.x;
    const float* row = qkv + (size_t)s * QKV3_ + h * HD_;
    float q = row[d];
    float k = row[INNER_ + d];
    float v = row[2 * INNER_ + d];

    __shared__ float sh[8];
    float sq = q * q, sk = k * k;
#pragma unroll
    for (int o = 16; o > 0; o >>= 1) {
        sq += __shfl_xor_sync(0xffffffffu, sq, o);
        sk += __shfl_xor_sync(0xffffffffu, sk, o);
    }
    int w = d >> 5;
    if ((d & 31) == 0) { sh[w] = sq; sh[4 + w] = sk; }
    __syncthreads();
    sq = sh[0] + sh[1] + sh[2] + sh[3];
    sk = sh[4] + sh[5] + sh[6] + sh[7];
    float rq = rsqrtf(sq * (1.f / HD_) + 1e-5f);
    float rk = rsqrtf(sk * (1.f / HD_) + 1e-5f);
    q = q * rq * wq[d];
    k = k * rk * wk[d];

    const int pos = pos_off + s;
    float c = rcos[pos * 64 + (d >> 1)];
    float sn = rsin[pos * 64 + (d >> 1)];
    float qo = __shfl_xor_sync(0xffffffffu, q, 1);
    float ko = __shfl_xor_sync(0xffffffffu, k, 1);
    float qr = (d & 1) ? (qo * sn + q * c) : (q * c - qo * sn);
    float kr = (d & 1) ? (ko * sn + k * c) : (k * c - ko * sn);

    qr *= SCALE2E_;

    size_t o = ((size_t)h * SALL_ + pos) * HD_ + d;
    qh[o] = __float2half(qr);
    kh[o] = __float2half(kr);
    vh[o] = __float2half(v);
}

// ---------------------------------------------------------------------------
// Tensor-core flash attention: Qh x Kh (1 product); P hi/lo x Vh (2 products).
// Epilogue writes fp16 hi/lo.
// ---------------------------------------------------------------------------
#define ALDA_ 136
#define ATTN_SMEM_ ((128 + 2 * 64) * ALDA_ * 2)

__global__ void __launch_bounds__(256, 1) attn_mma_kernel(
    const __half* __restrict__ Qh,
    const __half* __restrict__ Kh, const __half* __restrict__ Vh,
    __half* __restrict__ Oh, __half* __restrict__ Ol)
{
    extern __shared__ __half sbuf[];
    __half* sQh = sbuf;
    __half* sKh = sQh + 128 * ALDA_;
    __half* sVh = sKh + 64 * ALDA_;

    const int head = blockIdx.y;
    const int q0 = blockIdx.x * 128;
    const int tid = threadIdx.x;
    const int warp = tid >> 5, lane = tid & 31;
    const size_t hbase = (size_t)head * SALL_ * HD_;

    // Q tile: 128 rows x 128 halves = 2048 uint4; 8 iters x 256 threads.
    {
        const uint4* gqh = (const uint4*)(Qh + hbase + (size_t)q0 * HD_);
#pragma unroll
        for (int k = 0; k < 8; k++) {
            int i = tid + k * 256;
            int row = i >> 4, seg = i & 15;
            *(uint4*)&sQh[row * ALDA_ + seg * 8] = gqh[i];
        }
    }

    float accO[16][4];
#pragma unroll
    for (int i = 0; i < 16; i++)
#pragma unroll
        for (int e = 0; e < 4; e++) accO[i][e] = 0.f;
    float m0 = -1e30f, m1 = -1e30f, l0 = 0.f, l1 = 0.f;

    const int qa = lane >> 3, ra = lane & 7;
    const int arow = warp * 16 + (qa & 1) * 8 + ra;
    const int acol = (qa >> 1) * 8;
    const int vrow = lane & 15;
    const int vcol = (lane >> 4) * 8;

    for (int kt = 0; kt < SALL_ / 64; kt++) {
        __syncthreads();
        // K,V tiles: 64 rows x 128 halves = 1024 uint4 each; 4 iters x 256 thr.
        {
            const size_t kvoff = hbase + (size_t)(kt * 64) * HD_;
            const uint4* gkh = (const uint4*)(Kh + kvoff);
            const uint4* gvh = (const uint4*)(Vh + kvoff);
#pragma unroll
            for (int k = 0; k < 4; k++) {
                int i = tid + k * 256;
                int row = i >> 4, seg = i & 15;
                int dst = row * ALDA_ + seg * 8;
                *(uint4*)&sKh[dst] = gkh[i];
                *(uint4*)&sVh[dst] = gvh[i];
            }
        }
        __syncthreads();

        float accS[8][4];
#pragma unroll
        for (int j = 0; j < 8; j++)
#pragma unroll
            for (int e = 0; e < 4; e++) accS[j][e] = 0.f;

#pragma unroll
        for (int kc = 0; kc < 8; kc++) {
            uint32_t ah[4];
            ldsm_x4(ah, sptr(&sQh[arow * ALDA_ + kc * 16 + acol]));
#pragma unroll
            for (int np = 0; np < 4; np++) {
                uint32_t bh[4];
                int br = np * 16 + (qa & 1) * 8 + ra;
                ldsm_x4(bh, sptr(&sKh[br * ALDA_ + kc * 16 + acol]));
                mma_f16(accS[2 * np],     ah, bh[0], bh[2]);
                mma_f16(accS[2 * np + 1], ah, bh[1], bh[3]);
            }
        }

        float ml0 = -1e30f, ml1 = -1e30f;
#pragma unroll
        for (int j = 0; j < 8; j++) {
            ml0 = fmaxf(ml0, fmaxf(accS[j][0], accS[j][1]));
            ml1 = fmaxf(ml1, fmaxf(accS[j][2], accS[j][3]));
        }
#pragma unroll
        for (int o = 1; o < 4; o <<= 1) {
            ml0 = fmaxf(ml0, __shfl_xor_sync(0xffffffffu, ml0, o));
            ml1 = fmaxf(ml1, __shfl_xor_sync(0xffffffffu, ml1, o));
        }
        float mn0 = fmaxf(m0, ml0), mn1 = fmaxf(m1, ml1);
        float f0 = exp2f(m0 - mn0), f1 = exp2f(m1 - mn1);
        float s0 = 0.f, s1 = 0.f;
#pragma unroll
        for (int j = 0; j < 8; j++) {
            accS[j][0] = exp2f(accS[j][0] - mn0);
            accS[j][1] = exp2f(accS[j][1] - mn0);
            accS[j][2] = exp2f(accS[j][2] - mn1);
            accS[j][3] = exp2f(accS[j][3] - mn1);
            s0 += accS[j][0] + accS[j][1];
            s1 += accS[j][2] + accS[j][3];
        }
#pragma unroll
        for (int o = 1; o < 4; o <<= 1) {
            s0 += __shfl_xor_sync(0xffffffffu, s0, o);
            s1 += __shfl_xor_sync(0xffffffffu, s1, o);
        }
        l0 = l0 * f0 + s0; l1 = l1 * f1 + s1;
        m0 = mn0; m1 = mn1;
#pragma unroll
        for (int i = 0; i < 16; i++) {
            accO[i][0] *= f0; accO[i][1] *= f0;
            accO[i][2] *= f1; accO[i][3] *= f1;
        }

#pragma unroll
        for (int kc2 = 0; kc2 < 4; kc2++) {
            const int j0 = 2 * kc2, j1 = j0 + 1;
            uint32_t pah[4], pal[4];
            pah[0] = packh2(accS[j0][0], accS[j0][1]);
            pah[1] = packh2(accS[j0][2], accS[j0][3]);
            pah[2] = packh2(accS[j1][0], accS[j1][1]);
            pah[3] = packh2(accS[j1][2], accS[j1][3]);
            pal[0] = packh2(accS[j0][0] - lo16f(pah[0]), accS[j0][1] - hi16f(pah[0]));
            pal[1] = packh2(accS[j0][2] - lo16f(pah[1]), accS[j0][3] - hi16f(pah[1]));
            pal[2] = packh2(accS[j1][0] - lo16f(pah[2]), accS[j1][1] - hi16f(pah[2]));
            pal[3] = packh2(accS[j1][2] - lo16f(pah[3]), accS[j1][3] - hi16f(pah[3]));

            const int vr = kc2 * 16 + vrow;
#pragma unroll
            for (int np = 0; np < 8; np++) {
                uint32_t vbh[4];
                ldsm_x4_t(vbh, sptr(&sVh[vr * ALDA_ + np * 16 + vcol]));
                mma_f16(accO[2 * np],     pah, vbh[0], vbh[1]);
                mma_f16(accO[2 * np],     pal, vbh[0], vbh[1]);
                mma_f16(accO[2 * np + 1], pah, vbh[2], vbh[3]);
                mma_f16(accO[2 * np + 1], pal, vbh[2], vbh[3]);
            }
        }
    }

    // epilogue: normalize and emit fp16 hi/lo directly
    const float inv0 = 1.f / l0, inv1 = 1.f / l1;
    const int r0 = q0 + warp * 16 + (lane >> 2);
    const int cb = head * HD_ + (lane & 3) * 2;
#pragma unroll
    for (int nt = 0; nt < 16; nt++) {
        float x0 = accO[nt][0] * inv0, y0 = accO[nt][1] * inv0;
        float x1 = accO[nt][2] * inv1, y1 = accO[nt][3] * inv1;
        uint32_t h0 = packh2(x0, y0);
        uint32_t e0 = packh2(x0 - lo16f(h0), y0 - hi16f(h0));
        uint32_t h1 = packh2(x1, y1);
        uint32_t e1 = packh2(x1 - lo16f(h1), y1 - hi16f(h1));
        size_t o0 = (size_t)r0 * INNER_ + cb + nt * 8;
        size_t o1 = (size_t)(r0 + 8) * INNER_ + cb + nt * 8;
        *(uint32_t*)&Oh[o0] = h0;  *(uint32_t*)&Ol[o0] = e0;
        *(uint32_t*)&Oh[o1] = h1;  *(uint32_t*)&Ol[o1] = e1;
    }
}

// ---------------------------------------------------------------------------
static inline void conv_launch(const float* X, __half* h, long long n)
{
    int n4 = (int)(n >> 2);
    conv_f16_kernel<<<(n4 + 255) / 256, 256>>>(X, h, n4);
}

static inline void gemm_lr1(const __half* Ah, const __half* Bh,
                            const __half* LRh, const __half* UT,
                            const float* bias, float* C, int M, int N, int K)
{
    const int smem = 3 * (2 * 10240 + 10240);
    cudaFuncSetAttribute(gemm_mma2_kernel<1>,
                         cudaFuncAttributeMaxDynamicSharedMemorySize, smem);
    gemm_mma2_kernel<1><<<dim3(N / 256, M / 128), 256, smem>>>(
        Ah, nullptr, Bh, LRh, nullptr, UT, bias, C, M, N, K);
}

static inline void gemm_lr2(const __half* Ah, const __half* Al, const __half* Bh,
                            const __half* LRh, const __half* LRl, const __half* UT,
                            const float* bias, float* C, int M, int N, int K)
{
    const int smem = 3 * (3 * 10240 + 10240);
    cudaFuncSetAttribute(gemm_mma2_kernel<2>,
                         cudaFuncAttributeMaxDynamicSharedMemorySize, smem);
    gemm_mma2_kernel<2><<<dim3(N / 256, M / 128), 256, smem>>>(
        Ah, Al, Bh, LRh, LRl, UT, bias, C, M, N, K);
}

extern "C" void kernel_launch(void* const* d_in, const int* in_sizes, int n_in,
                              void* d_out, int out_size)
{
    const float* hs        = (const float*)d_in[0];
    const float* ehs       = (const float*)d_in[1];
    const float* rcos      = (const float*)d_in[2];
    const float* rsin      = (const float*)d_in[3];
    const float* qkv_w     = (const float*)d_in[4];
    const float* qkv_down  = (const float*)d_in[5];
    const float* qkv_up    = (const float*)d_in[6];
    const float* aqkv_w    = (const float*)d_in[7];
    const float* aqkv_down = (const float*)d_in[8];
    const float* aqkv_up   = (const float*)d_in[9];
    const float* out_w     = (const float*)d_in[10];
    const float* out_down  = (const float*)d_in[11];
    const float* out_up    = (const float*)d_in[12];
    const float* out_b     = (const float*)d_in[13];
    const float* aout_w    = (const float*)d_in[14];
    const float* aout_down = (const float*)d_in[15];
    const float* aout_up   = (const float*)d_in[16];
    const float* aout_b    = (const float*)d_in[17];
    const float* nq        = (const float*)d_in[18];
    const float* nk        = (const float*)d_in[19];
    const float* naq       = (const float*)d_in[20];
    const float* nak       = (const float*)d_in[21];

    float *qkv_img, *qkv_txt;
    cudaGetSymbolAddress((void**)&qkv_img, g_qkv_img);
    cudaGetSymbolAddress((void**)&qkv_txt, g_qkv_txt);

    __half *lrah, *lral, *lrbh, *lrbl;
    cudaGetSymbolAddress((void**)&lrah, g_lrah);
    cudaGetSymbolAddress((void**)&lral, g_lral);
    cudaGetSymbolAddress((void**)&lrbh, g_lrbh);
    cudaGetSymbolAddress((void**)&lrbl, g_lrbl);

    __half *UTq, *UTaq, *UTo, *UTao;
    cudaGetSymbolAddress((void**)&UTq, g_UTq);
    cudaGetSymbolAddress((void**)&UTaq, g_UTaq);
    cudaGetSymbolAddress((void**)&UTo, g_UTo);
    cudaGetSymbolAddress((void**)&UTao, g_UTao);

    __half *qbh, *kbh, *vbh, *ACh, *ACl;
    cudaGetSymbolAddress((void**)&qbh, g_qh);
    cudaGetSymbolAddress((void**)&kbh, g_kh);
    cudaGetSymbolAddress((void**)&vbh, g_vh);
    cudaGetSymbolAddress((void**)&ACh, g_ACh);
    cudaGetSymbolAddress((void**)&ACl, g_ACl);

    __half *Ai, *At, *Bq, *Baq, *Bo, *Bao;
    cudaGetSymbolAddress((void**)&Ai, g_Ai);
    cudaGetSymbolAddress((void**)&At, g_At);
    cudaGetSymbolAddress((void**)&Bq, g_Bq);
    cudaGetSymbolAddress((void**)&Baq, g_Baq);
    cudaGetSymbolAddress((void**)&Bo, g_Bo);
    cudaGetSymbolAddress((void**)&Bao, g_Bao);

    float* out_img = (float*)d_out;
    float* out_txt = (float*)d_out + (size_t)SIMG_ * D_;

    // ---- conversions ----
    conv_launch(hs,  Ai, (long long)SIMG_ * D_);
    conv_launch(ehs, At, (long long)STXT_ * D_);
    conv_launch(qkv_w,  Bq,  (long long)QKV3_ * D_);
    conv_launch(aqkv_w, Baq, (long long)QKV3_ * D_);
    conv_launch(out_w,  Bo,  (long long)D_ * INNER_);
    conv_launch(aout_w, Bao, (long long)D_ * INNER_);
    tconv_kernel<<<(32 * QKV3_ + 255) / 256, 256>>>(qkv_up,  UTq,  QKV3_);
    tconv_kernel<<<(32 * QKV3_ + 255) / 256, 256>>>(aqkv_up, UTaq, QKV3_);
    tconv_kernel<<<(32 * D_ + 255) / 256, 256>>>(out_up,  UTo,  D_);
    tconv_kernel<<<(32 * D_ + 255) / 256, 256>>>(aout_up, UTao, D_);

    // ---- QKV projections: 1-product fp16 GEMM + low-rank fold ----
    down_proj_f32_kernel<<<SIMG_, 256>>>(hs, qkv_down, lrah, lral, D_);
    gemm_lr1(Ai, Bq, lrah, UTq, nullptr, qkv_img, SIMG_, QKV3_, D_);
    down_proj_f32_kernel<<<STXT_, 256>>>(ehs, aqkv_down, lrbh, lrbl, D_);
    gemm_lr1(At, Baq, lrbh, UTaq, nullptr, qkv_txt, STXT_, QKV3_, D_);

    // ---- heads + RMSNorm + RoPE -> Q/K/V fp16 (txt first, then img) ----
    qkv_post_kernel<<<dim3(STXT_, H_), 128>>>(qkv_txt, 0, naq, nak, rcos, rsin,
                                              qbh, kbh, vbh);
    qkv_post_kernel<<<dim3(SIMG_, H_), 128>>>(qkv_img, STXT_, nq, nk, rcos, rsin,
                                              qbh, kbh, vbh);

    // ---- tensor-core attention (emits fp16 hi/lo activations) ----
    cudaFuncSetAttribute(attn_mma_kernel, cudaFuncAttributeMaxDynamicSharedMemorySize,
                         ATTN_SMEM_);
    attn_mma_kernel<<<dim3(SALL_ / 128, H_), 256, ATTN_SMEM_>>>(
        qbh, kbh, vbh, ACh, ACl);

    // ---- output projections: 2-product fp16 GEMM + low-rank fold ----
    const __half* Aimgh = ACh + (size_t)STXT_ * INNER_;
    const __half* Aimgl = ACl + (size_t)STXT_ * INNER_;
    const __half* Atxth = ACh;
    const __half* Atxtl = ACl;

    down_proj_hf_kernel<<<SIMG_, 256>>>(Aimgh, Aimgl, out_down, lrah, lral, INNER_);
    gemm_lr2(Aimgh, Aimgl, Bo, lrah, lral, UTo, out_b, out_img, SIMG_, D_, INNER_);
    down_proj_hf_kernel<<<STXT_, 256>>>(Atxth, Atxtl, aout_down, lrbh, lrbl, INNER_);
    gemm_lr2(Atxth, Atxtl, Bao, lrbh, lrbl, UTao, aout_b, out_txt, STXT_, D_, INNER_);
}